// round 8
// baseline (speedup 1.0000x reference)
#include <cuda_runtime.h>
#include <cuda_bf16.h>
#include <math.h>
#include <stdint.h>

// ---------------- problem constants ----------------
#define B_   4
#define L_   2048
#define C_   384
#define H_   12
#define N_   64
#define DI_  768
#define DI2_ 1536
#define HID_ 1536
#define PROJ_ 1676          // 2*DI + 2*N + H
#define M_   (B_*L_)        // 8192
#define EPS_ 1e-5f

#define Q_    64            // chunk length
#define NC_   32            // chunks per sequence (L/Q)
#define NBLK_ (2*B_*H_*NC_) // 3072

// ---------------- scratch (no allocations allowed) ----------------
__device__ float g_xln  [M_*C_];
__device__ float g_projf[M_*PROJ_];
__device__ float g_projb[M_*PROJ_];
__device__ float g_gated[M_*DI2_];     // [fwd(768) | bwd(768)] per row
__device__ float g_x2   [M_*C_];
__device__ float g_h2   [M_*C_];
__device__ float g_hid  [M_*HID_];
__device__ float g_wtf  [PROJ_*C_];    // Winf^T  (PROJ, C)
__device__ float g_wtb  [PROJ_*C_];    // Winb^T
__device__ float g_wcatT[C_*DI2_];     // [Woutf;Woutb]^T  (C, DI2)
__device__ float g_bcat [C_];
__device__ float g_ST   [(size_t)NBLK_*64*64];
__device__ float g_hp   [(size_t)NBLK_*64*64];
__device__ float g_dts  [NBLK_*Q_];
__device__ float g_css  [NBLK_*Q_];
__device__ float g_dtsum[NBLK_];

// ---------------- block reduction (128 threads) ----------------
__device__ __forceinline__ float blockSum128(float v) {
    __shared__ float sh[4];
    int lane = threadIdx.x & 31, w = threadIdx.x >> 5;
    #pragma unroll
    for (int o = 16; o; o >>= 1) v += __shfl_xor_sync(0xffffffffu, v, o);
    if (lane == 0) sh[w] = v;
    __syncthreads();
    float r = sh[0] + sh[1] + sh[2] + sh[3];
    __syncthreads();
    return r;
}

// ---------------- LayerNorm (row of 384) ----------------
__global__ void ln_kernel(const float* __restrict__ x,
                          const float* __restrict__ g,
                          const float* __restrict__ be,
                          float* __restrict__ o) {
    size_t row = blockIdx.x;
    const float* xr = x + row * C_;
    int t = threadIdx.x;
    float v0 = xr[t], v1 = xr[t + 128], v2 = xr[t + 256];
    float mu = blockSum128(v0 + v1 + v2) * (1.f / C_);
    float d0 = v0 - mu, d1 = v1 - mu, d2 = v2 - mu;
    float var = blockSum128(d0*d0 + d1*d1 + d2*d2) * (1.f / C_);
    float inv = rsqrtf(var + EPS_);
    float* orow = o + row * C_;
    orow[t]       = d0 * inv * g[t]       + be[t];
    orow[t + 128] = d1 * inv * g[t + 128] + be[t + 128];
    orow[t + 256] = d2 * inv * g[t + 256] + be[t + 256];
}

// ---------------- tiled weight transpose: dst[n*dstride + k] = src[k*N + n] --
__global__ void transpose_w(const float* __restrict__ src, float* __restrict__ dst,
                            int K, int N, int dstride) {
    __shared__ float t[32][33];
    int bx = blockIdx.x * 32, by = blockIdx.y * 32;  // bx along n, by along k
    int x = threadIdx.x, y = threadIdx.y;            // (32, 8)
    #pragma unroll
    for (int j = 0; j < 32; j += 8) {
        int k = by + y + j, n = bx + x;
        t[y + j][x] = (k < K && n < N) ? src[(size_t)k * N + n] : 0.f;
    }
    __syncthreads();
    #pragma unroll
    for (int j = 0; j < 32; j += 8) {
        int n = bx + y + j, k = by + x;
        if (n < N && k < K) dst[(size_t)n * dstride + k] = t[x][y + j];
    }
}

__global__ void prep_bias(const float* __restrict__ bf, const float* __restrict__ bb,
                          float* __restrict__ bcat) {
    int i = blockIdx.x * 256 + threadIdx.x;
    if (i < C_) bcat[i] = bf[i] + bb[i];
}

// ---------------- TF32 helpers ----------------
__device__ __forceinline__ uint32_t f2tf(float f) {
    uint32_t u; asm("cvt.rna.tf32.f32 %0, %1;" : "=r"(u) : "f"(f)); return u;
}
__device__ __forceinline__ void mma_tf32(float& d0, float& d1, float& d2, float& d3,
                                         uint32_t a0, uint32_t a1, uint32_t a2, uint32_t a3,
                                         uint32_t b0, uint32_t b1) {
    asm volatile("mma.sync.aligned.m16n8k8.row.col.f32.tf32.tf32.f32 "
                 "{%0,%1,%2,%3}, {%4,%5,%6,%7}, {%8,%9}, {%0,%1,%2,%3};\n"
                 : "+f"(d0), "+f"(d1), "+f"(d2), "+f"(d3)
                 : "r"(a0), "r"(a1), "r"(a2), "r"(a3), "r"(b0), "r"(b1));
}

// ---------------- TF32 tensor-core GEMM, permuted-k layout ------------------
// C[M,N] = A[M,K] @ Bt^T + bias (+ epilogue); Bt is (N,K) row-major.
// Smem layout: per 16-k tile, row-major [row][perm(k)], perm(k) = (k&3)*4 + (k>>2),
// row stride 20 words. A thread's m16n8k8 fragments for BOTH k8 steps are then one
// contiguous uint4 per row -> LDS.128.
// EPI: 0 = +bias; 1 = +bias,*bn_scale,+bn_bias,relu; 2 = +bias + residual(e1)
#define BM 128
#define BN 128
#define SA 20   // padded row stride (words)

template<int EPI>
__global__ __launch_bounds__(256, 2)
void gemm_kernel(const float* __restrict__ A, const float* __restrict__ Bt,
                 const float* __restrict__ bias, float* __restrict__ Cout,
                 int M, int N, int K,
                 const float* __restrict__ e1, const float* __restrict__ e2) {
    __shared__ uint32_t As[2][BM * SA];
    __shared__ uint32_t Bs[2][BN * SA];
    int tid = threadIdx.x;
    int gm0 = blockIdx.y << 7, gn0 = blockIdx.x << 7;

    // staging indices: thread handles rows r0 and r0+64, k-group q
    int r0 = tid >> 2;          // 0..63
    int qq = tid & 3;           // 0..3  -> global k offsets q, q+4, q+8, q+12

    // mma indices
    int lane = tid & 31, wid = tid >> 5;
    int wm = (wid >> 2) << 6;   // 0 / 64
    int wn = (wid & 3) << 5;    // 0,32,64,96
    int g = lane >> 2, tg = lane & 3;

    float sa[8], sb[8];

    // gather: 4 strided LDG.32 per (row, q) group
    auto gather = [&](int gk) {
        const float* Ap = A + (size_t)(gm0 + r0) * K + gk + qq;
        sa[0] = Ap[0]; sa[1] = Ap[4]; sa[2] = Ap[8]; sa[3] = Ap[12];
        const float* Ap2 = Ap + (size_t)64 * K;
        sa[4] = Ap2[0]; sa[5] = Ap2[4]; sa[6] = Ap2[8]; sa[7] = Ap2[12];
        int n1 = gn0 + r0, n2 = n1 + 64;
        if (n1 < N) {
            const float* Bp = Bt + (size_t)n1 * K + gk + qq;
            sb[0] = Bp[0]; sb[1] = Bp[4]; sb[2] = Bp[8]; sb[3] = Bp[12];
        } else { sb[0] = sb[1] = sb[2] = sb[3] = 0.f; }
        if (n2 < N) {
            const float* Bp = Bt + (size_t)n2 * K + gk + qq;
            sb[4] = Bp[0]; sb[5] = Bp[4]; sb[6] = Bp[8]; sb[7] = Bp[12];
        } else { sb[4] = sb[5] = sb[6] = sb[7] = 0.f; }
    };
    auto stage = [&](int buf) {
        uint4 v;
        v = make_uint4(f2tf(sa[0]), f2tf(sa[1]), f2tf(sa[2]), f2tf(sa[3]));
        *(uint4*)&As[buf][r0 * SA + qq * 4] = v;
        v = make_uint4(f2tf(sa[4]), f2tf(sa[5]), f2tf(sa[6]), f2tf(sa[7]));
        *(uint4*)&As[buf][(r0 + 64) * SA + qq * 4] = v;
        v = make_uint4(f2tf(sb[0]), f2tf(sb[1]), f2tf(sb[2]), f2tf(sb[3]));
        *(uint4*)&Bs[buf][r0 * SA + qq * 4] = v;
        v = make_uint4(f2tf(sb[4]), f2tf(sb[5]), f2tf(sb[6]), f2tf(sb[7]));
        *(uint4*)&Bs[buf][(r0 + 64) * SA + qq * 4] = v;
    };

    gather(0);
    stage(0);
    __syncthreads();

    float acc[4][4][4];
    #pragma unroll
    for (int i = 0; i < 4; i++)
        #pragma unroll
        for (int j = 0; j < 4; j++)
            #pragma unroll
            for (int r = 0; r < 4; r++) acc[i][j][r] = 0.f;

    int nkt = K >> 4;
    int buf = 0;
    for (int kt = 0; kt < nkt; ++kt) {
        if (kt + 1 < nkt) gather((kt + 1) << 4);

        // B fragments: one LDS.128 per j covers both k8 steps
        uint4 rB[4];
        #pragma unroll
        for (int j = 0; j < 4; j++)
            rB[j] = *(const uint4*)&Bs[buf][(wn + j * 8 + g) * SA + tg * 4];
        #pragma unroll
        for (int i = 0; i < 4; i++) {
            int m = wm + i * 16 + g;
            uint4 rA0 = *(const uint4*)&As[buf][m * SA + tg * 4];
            uint4 rA1 = *(const uint4*)&As[buf][(m + 8) * SA + tg * 4];
            #pragma unroll
            for (int j = 0; j < 4; j++) {
                // k8 step 0: k = tg, tg+4  (words .x, .y)
                mma_tf32(acc[i][j][0], acc[i][j][1], acc[i][j][2], acc[i][j][3],
                         rA0.x, rA1.x, rA0.y, rA1.y, rB[j].x, rB[j].y);
                // k8 step 1: k = 8+tg, 12+tg  (words .z, .w)
                mma_tf32(acc[i][j][0], acc[i][j][1], acc[i][j][2], acc[i][j][3],
                         rA0.z, rA1.z, rA0.w, rA1.w, rB[j].z, rB[j].w);
            }
        }
        if (kt + 1 < nkt) {
            stage(buf ^ 1);
            __syncthreads();
            buf ^= 1;
        }
    }

    // ---- epilogue (same acc layout as R6) ----
    const float bnrs = rsqrtf(1.f + EPS_);
    #pragma unroll
    for (int i = 0; i < 4; i++) {
        #pragma unroll
        for (int rh = 0; rh < 2; rh++) {
            int m = gm0 + wm + i * 16 + g + rh * 8;
            #pragma unroll
            for (int j = 0; j < 4; j++) {
                int n = gn0 + wn + j * 8 + 2 * tg;
                if (n < N) {
                    float v0 = acc[i][j][rh * 2 + 0] + bias[n];
                    float v1 = acc[i][j][rh * 2 + 1] + bias[n + 1];
                    if (EPI == 1) {
                        v0 = fmaxf(v0 * (e1[n] * bnrs) + e2[n], 0.f);
                        v1 = fmaxf(v1 * (e1[n + 1] * bnrs) + e2[n + 1], 0.f);
                    } else if (EPI == 2) {
                        const float* rp = e1 + (size_t)m * N + n;
                        v0 += rp[0]; v1 += rp[1];
                    }
                    float2 o2 = {v0, v1};
                    *(float2*)(Cout + (size_t)m * N + n) = o2;
                }
            }
        }
    }
}

// ============ chunked selective scan (unchanged) ============
__global__ __launch_bounds__(256)
void chunk_state_kernel(const float* __restrict__ projf, const float* __restrict__ projb,
                        const float* __restrict__ dtbf, const float* __restrict__ Alogf,
                        const float* __restrict__ dtbb, const float* __restrict__ Alogb,
                        float* __restrict__ ST, float* __restrict__ dts,
                        float* __restrict__ css, float* __restrict__ dtsum) {
    int blk = blockIdx.x;
    int c   = blk & (NC_ - 1);
    int h   = (blk >> 5) % H_;
    int b   = (blk / (NC_ * H_)) & (B_ - 1);
    int dir = blk / (NC_ * H_ * B_);
    const float* proj = dir ? projb : projf;
    float A    = -expf((dir ? Alogb : Alogf)[h]);
    float dtbh = (dir ? dtbb : dtbf)[h];

    __shared__ float Bsm[Q_ * 65];
    __shared__ float Xw [Q_ * 65];
    __shared__ float dsh[Q_], csh[Q_];

    int tid = threadIdx.x;
    if (tid < Q_) {
        int p = c * Q_ + tid;
        int l = dir ? (L_ - 1 - p) : p;
        float raw = proj[(size_t)(b * L_ + l) * PROJ_ + 2*DI_ + 2*N_ + h] + dtbh;
        float dt = (raw > 20.f) ? raw : log1pf(__expf(raw));
        dsh[tid] = dt;
        csh[tid] = dt;
    }
    __syncthreads();
    for (int off = 1; off < Q_; off <<= 1) {
        float v = 0.f;
        if (tid < Q_ && tid >= off) v = csh[tid - off];
        __syncthreads();
        if (tid < Q_ && tid >= off) csh[tid] += v;
        __syncthreads();
    }
    float cend = csh[Q_ - 1];
    if (tid < Q_) {
        dts[blk * Q_ + tid] = dsh[tid];
        css[blk * Q_ + tid] = csh[tid];
    }
    if (tid == 0) dtsum[blk] = cend;

    #pragma unroll
    for (int i = 0; i < 4; i++) {
        int s  = (tid >> 4) + i * 16;
        int c4 = (tid & 15) << 2;
        int p = c * Q_ + s;
        int l = dir ? (L_ - 1 - p) : p;
        const float* row = proj + (size_t)(b * L_ + l) * PROJ_;
        float4 bb = *(const float4*)(row + 2*DI_ + c4);
        float4 xx = *(const float4*)(row + DI_ + h*64 + c4);
        float w = __expf(A * (cend - csh[s])) * dsh[s];
        float* Bp = Bsm + s * 65 + c4;
        Bp[0] = bb.x; Bp[1] = bb.y; Bp[2] = bb.z; Bp[3] = bb.w;
        float* Xp = Xw + s * 65 + c4;
        Xp[0] = w * xx.x; Xp[1] = w * xx.y; Xp[2] = w * xx.z; Xp[3] = w * xx.w;
    }
    __syncthreads();

    int ty = tid >> 4, tx = tid & 15;
    float acc[4][4] = {};
    #pragma unroll 8
    for (int s = 0; s < Q_; s++) {
        float a0 = Bsm[s*65 + ty*4 + 0];
        float a1 = Bsm[s*65 + ty*4 + 1];
        float a2 = Bsm[s*65 + ty*4 + 2];
        float a3 = Bsm[s*65 + ty*4 + 3];
        float b0 = Xw[s*65 + tx*4 + 0];
        float b1 = Xw[s*65 + tx*4 + 1];
        float b2 = Xw[s*65 + tx*4 + 2];
        float b3 = Xw[s*65 + tx*4 + 3];
        acc[0][0] = fmaf(a0,b0,acc[0][0]); acc[0][1] = fmaf(a0,b1,acc[0][1]);
        acc[0][2] = fmaf(a0,b2,acc[0][2]); acc[0][3] = fmaf(a0,b3,acc[0][3]);
        acc[1][0] = fmaf(a1,b0,acc[1][0]); acc[1][1] = fmaf(a1,b1,acc[1][1]);
        acc[1][2] = fmaf(a1,b2,acc[1][2]); acc[1][3] = fmaf(a1,b3,acc[1][3]);
        acc[2][0] = fmaf(a2,b0,acc[2][0]); acc[2][1] = fmaf(a2,b1,acc[2][1]);
        acc[2][2] = fmaf(a2,b2,acc[2][2]); acc[2][3] = fmaf(a2,b3,acc[2][3]);
        acc[3][0] = fmaf(a3,b0,acc[3][0]); acc[3][1] = fmaf(a3,b1,acc[3][1]);
        acc[3][2] = fmaf(a3,b2,acc[3][2]); acc[3][3] = fmaf(a3,b3,acc[3][3]);
    }
    #pragma unroll
    for (int i = 0; i < 4; i++) {
        float4 v = {acc[i][0], acc[i][1], acc[i][2], acc[i][3]};
        *(float4*)(ST + (size_t)blk * 4096 + (ty*4 + i) * 64 + tx*4) = v;
    }
}

__global__ __launch_bounds__(256)
void state_pass_kernel(const float* __restrict__ ST, float* __restrict__ hp,
                       const float* __restrict__ dtsum,
                       const float* __restrict__ Alogf, const float* __restrict__ Alogb) {
    int g = blockIdx.x;
    int dir = g / (B_ * H_);
    int h = g % H_;
    float A = -expf((dir ? Alogb : Alogf)[h]);
    int t = threadIdx.x;
    float hreg[16];
    #pragma unroll
    for (int k = 0; k < 16; k++) hreg[k] = 0.f;
    size_t base = (size_t)g * NC_ * 4096;
    for (int cc = 0; cc < NC_; cc++) {
        size_t o = base + (size_t)cc * 4096 + t;
        float al = expf(A * dtsum[g * NC_ + cc]);
        float sv[16];
        #pragma unroll
        for (int k = 0; k < 16; k++) sv[k] = ST[o + k*256];
        #pragma unroll
        for (int k = 0; k < 16; k++) {
            hp[o + k*256] = hreg[k];
            hreg[k] = al * hreg[k] + sv[k];
        }
    }
}

extern __shared__ float smc[];
__global__ __launch_bounds__(256)
void chunk_out_kernel(const float* __restrict__ projf, const float* __restrict__ projb,
                      const float* __restrict__ Alogf, const float* __restrict__ Alogb,
                      const float* __restrict__ Df, const float* __restrict__ Db,
                      const float* __restrict__ dts, const float* __restrict__ css,
                      const float* __restrict__ hp, float* __restrict__ gated) {
    int blk = blockIdx.x;
    int c   = blk & (NC_ - 1);
    int h   = (blk >> 5) % H_;
    int b   = (blk / (NC_ * H_)) & (B_ - 1);
    int dir = blk / (NC_ * H_ * B_);
    const float* proj = dir ? projb : projf;
    const float* Dv   = dir ? Db : Df;
    float A = -expf((dir ? Alogb : Alogf)[h]);

    float* Csm = smc;
    float* Buf = smc + 64*65;
    float* Xsm = smc + 2*64*65;
    float* dsh = smc + 3*64*65;
    float* csh = dsh + 64;

    int tid = threadIdx.x;
    if (tid < Q_) {
        dsh[tid] = dts[blk * Q_ + tid];
        csh[tid] = css[blk * Q_ + tid];
    }
    #pragma unroll
    for (int i = 0; i < 4; i++) {
        int s  = (tid >> 4) + i * 16;
        int c4 = (tid & 15) << 2;
        int p = c * Q_ + s;
        int l = dir ? (L_ - 1 - p) : p;
        const float* row = proj + (size_t)(b * L_ + l) * PROJ_;
        float4 cc4 = *(const float4*)(row + 2*DI_ + N_ + c4);
        float4 bb4 = *(const float4*)(row + 2*DI_ + c4);
        float4 xx4 = *(const float4*)(row + DI_ + h*64 + c4);
        float* Cp = Csm + s*65 + c4;
        Cp[0] = cc4.x; Cp[1] = cc4.y; Cp[2] = cc4.z; Cp[3] = cc4.w;
        float* Bp = Buf + s*65 + c4;
        Bp[0] = bb4.x; Bp[1] = bb4.y; Bp[2] = bb4.z; Bp[3] = bb4.w;
        float* Xp = Xsm + s*65 + c4;
        Xp[0] = xx4.x; Xp[1] = xx4.y; Xp[2] = xx4.z; Xp[3] = xx4.w;
    }
    __syncthreads();

    int ty = tid >> 4, tx = tid & 15;

    float acc[4][4] = {};
    #pragma unroll 8
    for (int n = 0; n < 64; n++) {
        float a0 = Csm[(ty*4+0)*65 + n];
        float a1 = Csm[(ty*4+1)*65 + n];
        float a2 = Csm[(ty*4+2)*65 + n];
        float a3 = Csm[(ty*4+3)*65 + n];
        float b0 = Buf[(tx*4+0)*65 + n];
        float b1 = Buf[(tx*4+1)*65 + n];
        float b2 = Buf[(tx*4+2)*65 + n];
        float b3 = Buf[(tx*4+3)*65 + n];
        acc[0][0]=fmaf(a0,b0,acc[0][0]); acc[0][1]=fmaf(a0,b1,acc[0][1]);
        acc[0][2]=fmaf(a0,b2,acc[0][2]); acc[0][3]=fmaf(a0,b3,acc[0][3]);
        acc[1][0]=fmaf(a1,b0,acc[1][0]); acc[1][1]=fmaf(a1,b1,acc[1][1]);
        acc[1][2]=fmaf(a1,b2,acc[1][2]); acc[1][3]=fmaf(a1,b3,acc[1][3]);
        acc[2][0]=fmaf(a2,b0,acc[2][0]); acc[2][1]=fmaf(a2,b1,acc[2][1]);
        acc[2][2]=fmaf(a2,b2,acc[2][2]); acc[2][3]=fmaf(a2,b3,acc[2][3]);
        acc[3][0]=fmaf(a3,b0,acc[3][0]); acc[3][1]=fmaf(a3,b1,acc[3][1]);
        acc[3][2]=fmaf(a3,b2,acc[3][2]); acc[3][3]=fmaf(a3,b3,acc[3][3]);
    }
    __syncthreads();

    #pragma unroll
    for (int i = 0; i < 4; i++) {
        int t_ = ty*4 + i;
        #pragma unroll
        for (int j = 0; j < 4; j++) {
            int s_ = tx*4 + j;
            float m = (s_ <= t_) ? __expf(A * (csh[t_] - csh[s_])) * dsh[s_] : 0.f;
            Buf[t_*65 + s_] = acc[i][j] * m;
        }
    }
    __syncthreads();

    float y1[4][4] = {};
    #pragma unroll 8
    for (int s = 0; s < 64; s++) {
        float a0 = Buf[(ty*4+0)*65 + s];
        float a1 = Buf[(ty*4+1)*65 + s];
        float a2 = Buf[(ty*4+2)*65 + s];
        float a3 = Buf[(ty*4+3)*65 + s];
        float b0 = Xsm[s*65 + tx*4 + 0];
        float b1 = Xsm[s*65 + tx*4 + 1];
        float b2 = Xsm[s*65 + tx*4 + 2];
        float b3 = Xsm[s*65 + tx*4 + 3];
        y1[0][0]=fmaf(a0,b0,y1[0][0]); y1[0][1]=fmaf(a0,b1,y1[0][1]);
        y1[0][2]=fmaf(a0,b2,y1[0][2]); y1[0][3]=fmaf(a0,b3,y1[0][3]);
        y1[1][0]=fmaf(a1,b0,y1[1][0]); y1[1][1]=fmaf(a1,b1,y1[1][1]);
        y1[1][2]=fmaf(a1,b2,y1[1][2]); y1[1][3]=fmaf(a1,b3,y1[1][3]);
        y1[2][0]=fmaf(a2,b0,y1[2][0]); y1[2][1]=fmaf(a2,b1,y1[2][1]);
        y1[2][2]=fmaf(a2,b2,y1[2][2]); y1[2][3]=fmaf(a2,b3,y1[2][3]);
        y1[3][0]=fmaf(a3,b0,y1[3][0]); y1[3][1]=fmaf(a3,b1,y1[3][1]);
        y1[3][2]=fmaf(a3,b2,y1[3][2]); y1[3][3]=fmaf(a3,b3,y1[3][3]);
    }
    __syncthreads();

    #pragma unroll
    for (int i = 0; i < 4; i++) {
        int n  = (tid >> 4) + i * 16;
        int c4 = (tid & 15) << 2;
        float4 hh = *(const float4*)(hp + (size_t)blk * 4096 + n*64 + c4);
        float* Hp = Buf + n*65 + c4;
        Hp[0] = hh.x; Hp[1] = hh.y; Hp[2] = hh.z; Hp[3] = hh.w;
    }
    __syncthreads();

    float y2[4][4] = {};
    #pragma unroll 8
    for (int n = 0; n < 64; n++) {
        float a0 = Csm[(ty*4+0)*65 + n];
        float a1 = Csm[(ty*4+1)*65 + n];
        float a2 = Csm[(ty*4+2)*65 + n];
        float a3 = Csm[(ty*4+3)*65 + n];
        float b0 = Buf[n*65 + tx*4 + 0];
        float b1 = Buf[n*65 + tx*4 + 1];
        float b2 = Buf[n*65 + tx*4 + 2];
        float b3 = Buf[n*65 + tx*4 + 3];
        y2[0][0]=fmaf(a0,b0,y2[0][0]); y2[0][1]=fmaf(a0,b1,y2[0][1]);
        y2[0][2]=fmaf(a0,b2,y2[0][2]); y2[0][3]=fmaf(a0,b3,y2[0][3]);
        y2[1][0]=fmaf(a1,b0,y2[1][0]); y2[1][1]=fmaf(a1,b1,y2[1][1]);
        y2[1][2]=fmaf(a1,b2,y2[1][2]); y2[1][3]=fmaf(a1,b3,y2[1][3]);
        y2[2][0]=fmaf(a2,b0,y2[2][0]); y2[2][1]=fmaf(a2,b1,y2[2][1]);
        y2[2][2]=fmaf(a2,b2,y2[2][2]); y2[2][3]=fmaf(a2,b3,y2[2][3]);
        y2[3][0]=fmaf(a3,b0,y2[3][0]); y2[3][1]=fmaf(a3,b1,y2[3][1]);
        y2[3][2]=fmaf(a3,b2,y2[3][2]); y2[3][3]=fmaf(a3,b3,y2[3][3]);
    }

    float d0 = Dv[h*64 + tx*4 + 0];
    float d1 = Dv[h*64 + tx*4 + 1];
    float d2 = Dv[h*64 + tx*4 + 2];
    float d3 = Dv[h*64 + tx*4 + 3];
    #pragma unroll
    for (int i = 0; i < 4; i++) {
        int t_ = ty*4 + i;
        int p = c * Q_ + t_;
        int l = dir ? (L_ - 1 - p) : p;
        float lam = __expf(A * csh[t_]);
        const float* row = proj + (size_t)(b * L_ + l) * PROJ_;
        float4 zz = *(const float4*)(row + h*64 + tx*4);
        float xr0 = Xsm[t_*65 + tx*4 + 0];
        float xr1 = Xsm[t_*65 + tx*4 + 1];
        float xr2 = Xsm[t_*65 + tx*4 + 2];
        float xr3 = Xsm[t_*65 + tx*4 + 3];
        float4 o;
        float yv;
        yv = y1[i][0] + lam * y2[i][0] + d0 * xr0;
        o.x = yv * (zz.x / (1.f + __expf(-zz.x)));
        yv = y1[i][1] + lam * y2[i][1] + d1 * xr1;
        o.y = yv * (zz.y / (1.f + __expf(-zz.y)));
        yv = y1[i][2] + lam * y2[i][2] + d2 * xr2;
        o.z = yv * (zz.z / (1.f + __expf(-zz.z)));
        yv = y1[i][3] + lam * y2[i][3] + d3 * xr3;
        o.w = yv * (zz.w / (1.f + __expf(-zz.w)));
        *(float4*)(gated + (size_t)(b * L_ + l) * DI2_ + dir*DI_ + h*64 + tx*4) = o;
    }
}

// ---------------- host launch ----------------
static float* sym(const void* s) {
    void* p = nullptr;
    cudaGetSymbolAddress(&p, s);
    return (float*)p;
}

extern "C" void kernel_launch(void* const* d_in, const int* in_sizes, int n_in,
                              void* d_out, int out_size) {
    const float* points = (const float*)d_in[0];
    const float* g1  = (const float*)d_in[1];
    const float* be1 = (const float*)d_in[2];
    const float* g2  = (const float*)d_in[3];
    const float* be2 = (const float*)d_in[4];
    const float* Winf  = (const float*)d_in[5];
    const float* binf  = (const float*)d_in[6];
    const float* dtbf  = (const float*)d_in[7];
    const float* Alogf = (const float*)d_in[8];
    const float* Df    = (const float*)d_in[9];
    const float* Woutf = (const float*)d_in[10];
    const float* boutf = (const float*)d_in[11];
    const float* Winb  = (const float*)d_in[12];
    const float* binb  = (const float*)d_in[13];
    const float* dtbb  = (const float*)d_in[14];
    const float* Alogb = (const float*)d_in[15];
    const float* Db    = (const float*)d_in[16];
    const float* Woutb = (const float*)d_in[17];
    const float* boutb = (const float*)d_in[18];
    const float* W1  = (const float*)d_in[19];
    const float* b1m = (const float*)d_in[20];
    const float* bng = (const float*)d_in[21];
    const float* bnb = (const float*)d_in[22];
    const float* W2  = (const float*)d_in[23];
    const float* b2m = (const float*)d_in[24];
    float* out = (float*)d_out;

    float* xln   = sym(g_xln);
    float* projf = sym(g_projf);
    float* projb = sym(g_projb);
    float* gated = sym(g_gated);
    float* x2    = sym(g_x2);
    float* h2    = sym(g_h2);
    float* hid   = sym(g_hid);
    float* wtf   = sym(g_wtf);
    float* wtb   = sym(g_wtb);
    float* wcatT = sym(g_wcatT);
    float* bcat  = sym(g_bcat);
    float* ST    = sym(g_ST);
    float* hp    = sym(g_hp);
    float* dts   = sym(g_dts);
    float* css   = sym(g_css);
    float* dtsum = sym(g_dtsum);

    int smemC = (3 * 64 * 65 + 128) * sizeof(float);
    cudaFuncSetAttribute(chunk_out_kernel, cudaFuncAttributeMaxDynamicSharedMemorySize, smemC);

    // 1. LN1
    ln_kernel<<<M_, 128>>>(points, g1, be1, xln);

    // 1b. transpose weights to (N,K) layouts
    dim3 tb(32, 8);
    transpose_w<<<dim3((PROJ_ + 31) / 32, (C_ + 31) / 32), tb>>>(Winf, wtf, C_, PROJ_, C_);
    transpose_w<<<dim3((PROJ_ + 31) / 32, (C_ + 31) / 32), tb>>>(Winb, wtb, C_, PROJ_, C_);
    transpose_w<<<dim3((C_ + 31) / 32, (DI_ + 31) / 32), tb>>>(Woutf, wcatT, DI_, C_, DI2_);
    transpose_w<<<dim3((C_ + 31) / 32, (DI_ + 31) / 32), tb>>>(Woutb, wcatT + DI_, DI_, C_, DI2_);
    prep_bias<<<(C_ + 255) / 256, 256>>>(boutf, boutb, bcat);

    // 2/3. input projections
    dim3 gproj((PROJ_ + 127) / 128, M_ / 128);
    gemm_kernel<0><<<gproj, 256>>>(xln, wtf, binf, projf, M_, PROJ_, C_, nullptr, nullptr);
    gemm_kernel<0><<<gproj, 256>>>(xln, wtb, binb, projb, M_, PROJ_, C_, nullptr, nullptr);

    // 4. chunked bidirectional scan
    chunk_state_kernel<<<NBLK_, 256>>>(projf, projb, dtbf, Alogf, dtbb, Alogb,
                                       ST, dts, css, dtsum);
    state_pass_kernel<<<2 * B_ * H_, 256>>>(ST, hp, dtsum, Alogf, Alogb);
    chunk_out_kernel<<<NBLK_, 256, smemC>>>(projf, projb, Alogf, Alogb, Df, Db,
                                            dts, css, hp, gated);

    // 5. fused output projection + residual -> x2
    dim3 gwout(C_ / 128, M_ / 128);
    gemm_kernel<2><<<gwout, 256>>>(gated, wcatT, bcat, x2, M_, C_, DI2_, points, nullptr);

    // 6. LN2
    ln_kernel<<<M_, 128>>>(x2, g2, be2, h2);

    // 7. MLP up (W1 already (N,K))
    dim3 gmlp1(HID_ / 128, M_ / 128);
    gemm_kernel<1><<<gmlp1, 256>>>(h2, W1, b1m, hid, M_, HID_, C_, bng, bnb);

    // 8. MLP down + residual -> d_out (W2 already (N,K))
    dim3 gmlp2(C_ / 128, M_ / 128);
    gemm_kernel<2><<<gmlp2, 256>>>(hid, W2, b2m, out, M_, C_, HID_, x2, nullptr);
}

// round 9
// speedup vs baseline: 1.6954x; 1.6954x over previous
#include <cuda_runtime.h>
#include <cuda_bf16.h>
#include <math.h>
#include <stdint.h>

// ---------------- problem constants ----------------
#define B_   4
#define L_   2048
#define C_   384
#define H_   12
#define N_   64
#define DI_  768
#define DI2_ 1536
#define HID_ 1536
#define PROJ_ 1676          // 2*DI + 2*N + H
#define M_   (B_*L_)        // 8192
#define EPS_ 1e-5f

#define Q_    64            // chunk length
#define NC_   32            // chunks per sequence (L/Q)
#define NBLK_ (2*B_*H_*NC_) // 3072

// ---------------- scratch (no allocations allowed) ----------------
__device__ float g_xln  [M_*C_];
__device__ float g_projf[M_*PROJ_];
__device__ float g_projb[M_*PROJ_];
__device__ float g_gated[M_*DI2_];     // [fwd(768) | bwd(768)] per row, tf32-rounded
__device__ float g_x2   [M_*C_];
__device__ float g_h2   [M_*C_];
__device__ float g_hid  [M_*HID_];
__device__ float g_wtf  [PROJ_*C_];    // Winf^T  (PROJ, C), tf32-rounded
__device__ float g_wtb  [PROJ_*C_];
__device__ float g_wcatT[C_*DI2_];     // [Woutf;Woutb]^T  (C, DI2), tf32-rounded
__device__ float g_w1c  [HID_*C_];     // W1 tf32-rounded
__device__ float g_w2c  [C_*HID_];     // W2 tf32-rounded
__device__ float g_bcat [C_];
__device__ float g_ST   [(size_t)NBLK_*64*64];
__device__ float g_hp   [(size_t)NBLK_*64*64];
__device__ float g_dts  [NBLK_*Q_];
__device__ float g_css  [NBLK_*Q_];
__device__ float g_dtsum[NBLK_];

// ---------------- helpers ----------------
__device__ __forceinline__ uint32_t smem_u32(const void* p) {
    uint32_t a;
    asm("{ .reg .u64 t; cvta.to.shared.u64 t, %1; cvt.u32.u64 %0, t; }" : "=r"(a) : "l"(p));
    return a;
}
__device__ __forceinline__ uint32_t f2tf(float f) {
    uint32_t u; asm("cvt.rna.tf32.f32 %0, %1;" : "=r"(u) : "f"(f)); return u;
}
__device__ __forceinline__ float f2tff(float f) {
    return __uint_as_float(f2tf(f));
}
__device__ __forceinline__ void mma_tf32(float& d0, float& d1, float& d2, float& d3,
                                         uint32_t a0, uint32_t a1, uint32_t a2, uint32_t a3,
                                         uint32_t b0, uint32_t b1) {
    asm volatile("mma.sync.aligned.m16n8k8.row.col.f32.tf32.tf32.f32 "
                 "{%0,%1,%2,%3}, {%4,%5,%6,%7}, {%8,%9}, {%0,%1,%2,%3};\n"
                 : "+f"(d0), "+f"(d1), "+f"(d2), "+f"(d3)
                 : "r"(a0), "r"(a1), "r"(a2), "r"(a3), "r"(b0), "r"(b1));
}
#define LDSM4(d0,d1,d2,d3,addr) \
    asm volatile("ldmatrix.sync.aligned.m8n8.x4.shared.b16 {%0,%1,%2,%3}, [%4];" \
        : "=r"(d0), "=r"(d1), "=r"(d2), "=r"(d3) : "r"(addr))
#define CP_ASYNC(dst, src) \
    asm volatile("cp.async.ca.shared.global [%0], [%1], 16;" :: "r"(dst), "l"(src))
#define CP_ASYNC_Z(dst, src, sz) \
    asm volatile("cp.async.ca.shared.global [%0], [%1], 16, %2;" :: "r"(dst), "l"(src), "r"(sz))
#define CP_COMMIT() asm volatile("cp.async.commit_group;" ::: "memory")
#define CP_WAIT1()  asm volatile("cp.async.wait_group 1;" ::: "memory")

// ---------------- block reduction (128 threads) ----------------
__device__ __forceinline__ float blockSum128(float v) {
    __shared__ float sh[4];
    int lane = threadIdx.x & 31, w = threadIdx.x >> 5;
    #pragma unroll
    for (int o = 16; o; o >>= 1) v += __shfl_xor_sync(0xffffffffu, v, o);
    if (lane == 0) sh[w] = v;
    __syncthreads();
    float r = sh[0] + sh[1] + sh[2] + sh[3];
    __syncthreads();
    return r;
}

// ---------------- LayerNorm (row of 384), output tf32-rounded ----------------
__global__ void ln_kernel(const float* __restrict__ x,
                          const float* __restrict__ g,
                          const float* __restrict__ be,
                          float* __restrict__ o) {
    size_t row = blockIdx.x;
    const float* xr = x + row * C_;
    int t = threadIdx.x;
    float v0 = xr[t], v1 = xr[t + 128], v2 = xr[t + 256];
    float mu = blockSum128(v0 + v1 + v2) * (1.f / C_);
    float d0 = v0 - mu, d1 = v1 - mu, d2 = v2 - mu;
    float var = blockSum128(d0*d0 + d1*d1 + d2*d2) * (1.f / C_);
    float inv = rsqrtf(var + EPS_);
    float* orow = o + row * C_;
    orow[t]       = f2tff(d0 * inv * g[t]       + be[t]);
    orow[t + 128] = f2tff(d1 * inv * g[t + 128] + be[t + 128]);
    orow[t + 256] = f2tff(d2 * inv * g[t + 256] + be[t + 256]);
}

// ---------------- tiled weight transpose (+ tf32 round) ---------------------
__global__ void transpose_w(const float* __restrict__ src, float* __restrict__ dst,
                            int K, int N, int dstride) {
    __shared__ float t[32][33];
    int bx = blockIdx.x * 32, by = blockIdx.y * 32;
    int x = threadIdx.x, y = threadIdx.y;            // (32, 8)
    #pragma unroll
    for (int j = 0; j < 32; j += 8) {
        int k = by + y + j, n = bx + x;
        t[y + j][x] = (k < K && n < N) ? src[(size_t)k * N + n] : 0.f;
    }
    __syncthreads();
    #pragma unroll
    for (int j = 0; j < 32; j += 8) {
        int n = bx + y + j, k = by + x;
        if (n < N && k < K) dst[(size_t)n * dstride + k] = f2tff(t[x][y + j]);
    }
}

__global__ void cvt_copy(const float* __restrict__ src, float* __restrict__ dst, int n) {
    int i = (blockIdx.x * 256 + threadIdx.x) * 4;
    if (i < n) {
        float4 v = *(const float4*)(src + i);
        v.x = f2tff(v.x); v.y = f2tff(v.y); v.z = f2tff(v.z); v.w = f2tff(v.w);
        *(float4*)(dst + i) = v;
    }
}

__global__ void prep_bias(const float* __restrict__ bf, const float* __restrict__ bb,
                          float* __restrict__ bcat) {
    int i = blockIdx.x * 256 + threadIdx.x;
    if (i < C_) bcat[i] = bf[i] + bb[i];
}

// ---------------- TF32 GEMM: cp.async 3-stage + ldmatrix --------------------
// C[M,N] = A[M,K] @ Bt^T + bias (+ epilogue); Bt is (N,K) row-major.
// A, Bt are pre-rounded to tf32 (rna) by producers.
// Smem per stage: A[128][20] + B[128][20] words (row-major, stride 20).
// EPI: 0 = +bias; 1 = +bias,*bn_scale,+bn_bias,relu (output tf32-rounded);
//      2 = +bias + residual(e1)
#define SA 20
#define AS_WORDS (128 * SA)
#define STAGE_WORDS (2 * AS_WORDS)
#define GSMEM_BYTES (3 * STAGE_WORDS * 4)   // 61440

template<int EPI>
__global__ __launch_bounds__(256, 2)
void gemm_kernel(const float* __restrict__ A, const float* __restrict__ Bt,
                 const float* __restrict__ bias, float* __restrict__ Cout,
                 int M, int N, int K,
                 const float* __restrict__ e1, const float* __restrict__ e2) {
    extern __shared__ uint32_t smg[];
    uint32_t sbase = smem_u32(smg);
    int tid = threadIdx.x;
    int gm0 = blockIdx.y << 7, gn0 = blockIdx.x << 7;
    int lane = tid & 31, wid = tid >> 5;
    int wm = (wid >> 2) << 6;   // 0 / 64
    int wn = (wid & 3) << 5;    // 0,32,64,96
    int g = lane >> 2, tg = lane & 3;

    // ldmatrix lane base offsets (words)
    int aoff = (wm + (lane & 15)) * SA + ((lane >> 4) << 2);
    int boff = (wn + (lane & 7) + ((lane >> 4) << 3)) * SA + (((lane >> 3) & 1) << 2);

    // cp.async issue of one k16 tile into stage stg
    auto issue = [&](int kt, int stg) {
        int gk = kt << 4;
        uint32_t sA = sbase + stg * (STAGE_WORDS * 4);
        uint32_t sB = sA + AS_WORDS * 4;
        #pragma unroll
        for (int h = 0; h < 2; h++) {
            int seg = tid + (h << 8);
            int row = seg >> 2, k4 = (seg & 3) << 2;
            uint32_t da = sA + (row * SA + k4) * 4;
            const float* ga = A + (size_t)(gm0 + row) * K + gk + k4;
            CP_ASYNC(da, ga);
            uint32_t db = sB + (row * SA + k4) * 4;
            const float* gb = Bt + (size_t)(gn0 + row) * K + gk + k4;
            int sz = (gn0 + row < N) ? 16 : 0;
            CP_ASYNC_Z(db, gb, sz);
        }
    };

    float acc[4][4][4];
    #pragma unroll
    for (int i = 0; i < 4; i++)
        #pragma unroll
        for (int j = 0; j < 4; j++)
            #pragma unroll
            for (int r = 0; r < 4; r++) acc[i][j][r] = 0.f;

    int nkt = K >> 4;
    issue(0, 0); CP_COMMIT();
    issue(1, 1); CP_COMMIT();

    for (int kt = 0; kt < nkt; kt++) {
        CP_WAIT1();
        __syncthreads();
        int stg = kt % 3;
        if (kt + 2 < nkt) issue(kt + 2, (kt + 2) % 3);
        CP_COMMIT();

        uint32_t sA = sbase + stg * (STAGE_WORDS * 4);
        uint32_t sB = sA + AS_WORDS * 4;
        uint32_t aaddr = sA + aoff * 4;
        uint32_t baddr = sB + boff * 4;

        // B fragments: jj in {0,1} covers j pairs (2jj, 2jj+1); kh in {0,1} = k8 halves
        uint32_t rb[2][2][4];
        #pragma unroll
        for (int jj = 0; jj < 2; jj++)
            #pragma unroll
            for (int kh = 0; kh < 2; kh++)
                LDSM4(rb[jj][kh][0], rb[jj][kh][1], rb[jj][kh][2], rb[jj][kh][3],
                      baddr + ((jj * 16 * SA) + kh * 8) * 4);

        #pragma unroll
        for (int i = 0; i < 4; i++) {
            #pragma unroll
            for (int kh = 0; kh < 2; kh++) {
                uint32_t a0, a1, a2, a3;
                LDSM4(a0, a1, a2, a3, aaddr + ((i * 16 * SA) + kh * 8) * 4);
                #pragma unroll
                for (int j = 0; j < 4; j++) {
                    int jj = j >> 1, jl = j & 1;
                    mma_tf32(acc[i][j][0], acc[i][j][1], acc[i][j][2], acc[i][j][3],
                             a0, a1, a2, a3,
                             rb[jj][kh][jl * 2], rb[jj][kh][jl * 2 + 1]);
                }
            }
        }
    }

    // ---- epilogue ----
    const float bnrs = rsqrtf(1.f + EPS_);
    #pragma unroll
    for (int i = 0; i < 4; i++) {
        #pragma unroll
        for (int rh = 0; rh < 2; rh++) {
            int m = gm0 + wm + i * 16 + g + rh * 8;
            #pragma unroll
            for (int j = 0; j < 4; j++) {
                int n = gn0 + wn + j * 8 + 2 * tg;
                if (n < N) {
                    float v0 = acc[i][j][rh * 2 + 0] + bias[n];
                    float v1 = acc[i][j][rh * 2 + 1] + bias[n + 1];
                    if (EPI == 1) {
                        v0 = fmaxf(v0 * (e1[n] * bnrs) + e2[n], 0.f);
                        v1 = fmaxf(v1 * (e1[n + 1] * bnrs) + e2[n + 1], 0.f);
                        v0 = f2tff(v0); v1 = f2tff(v1);  // hid feeds next GEMM
                    } else if (EPI == 2) {
                        const float* rp = e1 + (size_t)m * N + n;
                        v0 += rp[0]; v1 += rp[1];
                    }
                    float2 o2 = {v0, v1};
                    *(float2*)(Cout + (size_t)m * N + n) = o2;
                }
            }
        }
    }
}

// ============ chunked selective scan ============
__global__ __launch_bounds__(256)
void chunk_state_kernel(const float* __restrict__ projf, const float* __restrict__ projb,
                        const float* __restrict__ dtbf, const float* __restrict__ Alogf,
                        const float* __restrict__ dtbb, const float* __restrict__ Alogb,
                        float* __restrict__ ST, float* __restrict__ dts,
                        float* __restrict__ css, float* __restrict__ dtsum) {
    int blk = blockIdx.x;
    int c   = blk & (NC_ - 1);
    int h   = (blk >> 5) % H_;
    int b   = (blk / (NC_ * H_)) & (B_ - 1);
    int dir = blk / (NC_ * H_ * B_);
    const float* proj = dir ? projb : projf;
    float A    = -expf((dir ? Alogb : Alogf)[h]);
    float dtbh = (dir ? dtbb : dtbf)[h];

    __shared__ float Bsm[Q_ * 65];
    __shared__ float Xw [Q_ * 65];
    __shared__ float dsh[Q_], csh[Q_];

    int tid = threadIdx.x;
    if (tid < Q_) {
        int p = c * Q_ + tid;
        int l = dir ? (L_ - 1 - p) : p;
        float raw = proj[(size_t)(b * L_ + l) * PROJ_ + 2*DI_ + 2*N_ + h] + dtbh;
        float dt = (raw > 20.f) ? raw : log1pf(__expf(raw));
        dsh[tid] = dt;
        csh[tid] = dt;
    }
    __syncthreads();
    for (int off = 1; off < Q_; off <<= 1) {
        float v = 0.f;
        if (tid < Q_ && tid >= off) v = csh[tid - off];
        __syncthreads();
        if (tid < Q_ && tid >= off) csh[tid] += v;
        __syncthreads();
    }
    float cend = csh[Q_ - 1];
    if (tid < Q_) {
        dts[blk * Q_ + tid] = dsh[tid];
        css[blk * Q_ + tid] = csh[tid];
    }
    if (tid == 0) dtsum[blk] = cend;

    #pragma unroll
    for (int i = 0; i < 4; i++) {
        int s  = (tid >> 4) + i * 16;
        int c4 = (tid & 15) << 2;
        int p = c * Q_ + s;
        int l = dir ? (L_ - 1 - p) : p;
        const float* row = proj + (size_t)(b * L_ + l) * PROJ_;
        float4 bb = *(const float4*)(row + 2*DI_ + c4);
        float4 xx = *(const float4*)(row + DI_ + h*64 + c4);
        float w = __expf(A * (cend - csh[s])) * dsh[s];
        float* Bp = Bsm + s * 65 + c4;
        Bp[0] = bb.x; Bp[1] = bb.y; Bp[2] = bb.z; Bp[3] = bb.w;
        float* Xp = Xw + s * 65 + c4;
        Xp[0] = w * xx.x; Xp[1] = w * xx.y; Xp[2] = w * xx.z; Xp[3] = w * xx.w;
    }
    __syncthreads();

    int ty = tid >> 4, tx = tid & 15;
    float acc[4][4] = {};
    #pragma unroll 8
    for (int s = 0; s < Q_; s++) {
        float a0 = Bsm[s*65 + ty*4 + 0];
        float a1 = Bsm[s*65 + ty*4 + 1];
        float a2 = Bsm[s*65 + ty*4 + 2];
        float a3 = Bsm[s*65 + ty*4 + 3];
        float b0 = Xw[s*65 + tx*4 + 0];
        float b1 = Xw[s*65 + tx*4 + 1];
        float b2 = Xw[s*65 + tx*4 + 2];
        float b3 = Xw[s*65 + tx*4 + 3];
        acc[0][0] = fmaf(a0,b0,acc[0][0]); acc[0][1] = fmaf(a0,b1,acc[0][1]);
        acc[0][2] = fmaf(a0,b2,acc[0][2]); acc[0][3] = fmaf(a0,b3,acc[0][3]);
        acc[1][0] = fmaf(a1,b0,acc[1][0]); acc[1][1] = fmaf(a1,b1,acc[1][1]);
        acc[1][2] = fmaf(a1,b2,acc[1][2]); acc[1][3] = fmaf(a1,b3,acc[1][3]);
        acc[2][0] = fmaf(a2,b0,acc[2][0]); acc[2][1] = fmaf(a2,b1,acc[2][1]);
        acc[2][2] = fmaf(a2,b2,acc[2][2]); acc[2][3] = fmaf(a2,b3,acc[2][3]);
        acc[3][0] = fmaf(a3,b0,acc[3][0]); acc[3][1] = fmaf(a3,b1,acc[3][1]);
        acc[3][2] = fmaf(a3,b2,acc[3][2]); acc[3][3] = fmaf(a3,b3,acc[3][3]);
    }
    #pragma unroll
    for (int i = 0; i < 4; i++) {
        float4 v = {acc[i][0], acc[i][1], acc[i][2], acc[i][3]};
        *(float4*)(ST + (size_t)blk * 4096 + (ty*4 + i) * 64 + tx*4) = v;
    }
}

__global__ __launch_bounds__(256)
void state_pass_kernel(const float* __restrict__ ST, float* __restrict__ hp,
                       const float* __restrict__ dtsum,
                       const float* __restrict__ Alogf, const float* __restrict__ Alogb) {
    int g = blockIdx.x;
    int dir = g / (B_ * H_);
    int h = g % H_;
    float A = -expf((dir ? Alogb : Alogf)[h]);
    int t = threadIdx.x;
    float hreg[16];
    #pragma unroll
    for (int k = 0; k < 16; k++) hreg[k] = 0.f;
    size_t base = (size_t)g * NC_ * 4096;
    for (int cc = 0; cc < NC_; cc++) {
        size_t o = base + (size_t)cc * 4096 + t;
        float al = expf(A * dtsum[g * NC_ + cc]);
        float sv[16];
        #pragma unroll
        for (int k = 0; k < 16; k++) sv[k] = ST[o + k*256];
        #pragma unroll
        for (int k = 0; k < 16; k++) {
            hp[o + k*256] = hreg[k];
            hreg[k] = al * hreg[k] + sv[k];
        }
    }
}

extern __shared__ float smc[];
__global__ __launch_bounds__(256)
void chunk_out_kernel(const float* __restrict__ projf, const float* __restrict__ projb,
                      const float* __restrict__ Alogf, const float* __restrict__ Alogb,
                      const float* __restrict__ Df, const float* __restrict__ Db,
                      const float* __restrict__ dts, const float* __restrict__ css,
                      const float* __restrict__ hp, float* __restrict__ gated) {
    int blk = blockIdx.x;
    int c   = blk & (NC_ - 1);
    int h   = (blk >> 5) % H_;
    int b   = (blk / (NC_ * H_)) & (B_ - 1);
    int dir = blk / (NC_ * H_ * B_);
    const float* proj = dir ? projb : projf;
    const float* Dv   = dir ? Db : Df;
    float A = -expf((dir ? Alogb : Alogf)[h]);

    float* Csm = smc;
    float* Buf = smc + 64*65;
    float* Xsm = smc + 2*64*65;
    float* dsh = smc + 3*64*65;
    float* csh = dsh + 64;

    int tid = threadIdx.x;
    if (tid < Q_) {
        dsh[tid] = dts[blk * Q_ + tid];
        csh[tid] = css[blk * Q_ + tid];
    }
    #pragma unroll
    for (int i = 0; i < 4; i++) {
        int s  = (tid >> 4) + i * 16;
        int c4 = (tid & 15) << 2;
        int p = c * Q_ + s;
        int l = dir ? (L_ - 1 - p) : p;
        const float* row = proj + (size_t)(b * L_ + l) * PROJ_;
        float4 cc4 = *(const float4*)(row + 2*DI_ + N_ + c4);
        float4 bb4 = *(const float4*)(row + 2*DI_ + c4);
        float4 xx4 = *(const float4*)(row + DI_ + h*64 + c4);
        float* Cp = Csm + s*65 + c4;
        Cp[0] = cc4.x; Cp[1] = cc4.y; Cp[2] = cc4.z; Cp[3] = cc4.w;
        float* Bp = Buf + s*65 + c4;
        Bp[0] = bb4.x; Bp[1] = bb4.y; Bp[2] = bb4.z; Bp[3] = bb4.w;
        float* Xp = Xsm + s*65 + c4;
        Xp[0] = xx4.x; Xp[1] = xx4.y; Xp[2] = xx4.z; Xp[3] = xx4.w;
    }
    __syncthreads();

    int ty = tid >> 4, tx = tid & 15;

    float acc[4][4] = {};
    #pragma unroll 8
    for (int n = 0; n < 64; n++) {
        float a0 = Csm[(ty*4+0)*65 + n];
        float a1 = Csm[(ty*4+1)*65 + n];
        float a2 = Csm[(ty*4+2)*65 + n];
        float a3 = Csm[(ty*4+3)*65 + n];
        float b0 = Buf[(tx*4+0)*65 + n];
        float b1 = Buf[(tx*4+1)*65 + n];
        float b2 = Buf[(tx*4+2)*65 + n];
        float b3 = Buf[(tx*4+3)*65 + n];
        acc[0][0]=fmaf(a0,b0,acc[0][0]); acc[0][1]=fmaf(a0,b1,acc[0][1]);
        acc[0][2]=fmaf(a0,b2,acc[0][2]); acc[0][3]=fmaf(a0,b3,acc[0][3]);
        acc[1][0]=fmaf(a1,b0,acc[1][0]); acc[1][1]=fmaf(a1,b1,acc[1][1]);
        acc[1][2]=fmaf(a1,b2,acc[1][2]); acc[1][3]=fmaf(a1,b3,acc[1][3]);
        acc[2][0]=fmaf(a2,b0,acc[2][0]); acc[2][1]=fmaf(a2,b1,acc[2][1]);
        acc[2][2]=fmaf(a2,b2,acc[2][2]); acc[2][3]=fmaf(a2,b3,acc[2][3]);
        acc[3][0]=fmaf(a3,b0,acc[3][0]); acc[3][1]=fmaf(a3,b1,acc[3][1]);
        acc[3][2]=fmaf(a3,b2,acc[3][2]); acc[3][3]=fmaf(a3,b3,acc[3][3]);
    }
    __syncthreads();

    #pragma unroll
    for (int i = 0; i < 4; i++) {
        int t_ = ty*4 + i;
        #pragma unroll
        for (int j = 0; j < 4; j++) {
            int s_ = tx*4 + j;
            float m = (s_ <= t_) ? __expf(A * (csh[t_] - csh[s_])) * dsh[s_] : 0.f;
            Buf[t_*65 + s_] = acc[i][j] * m;
        }
    }
    __syncthreads();

    float y1[4][4] = {};
    #pragma unroll 8
    for (int s = 0; s < 64; s++) {
        float a0 = Buf[(ty*4+0)*65 + s];
        float a1 = Buf[(ty*4+1)*65 + s];
        float a2 = Buf[(ty*4+2)*65 + s];
        float a3 = Buf[(ty*4+3)*65 + s];
        float b0 = Xsm[s*65 + tx*4 + 0];
        float b1 = Xsm[s*65 + tx*4 + 1];
        float b2 = Xsm[s*65 + tx*4 + 2];
        float b3 = Xsm[s*65 + tx*4 + 3];
        y1[0][0]=fmaf(a0,b0,y1[0][0]); y1[0][1]=fmaf(a0,b1,y1[0][1]);
        y1[0][2]=fmaf(a0,b2,y1[0][2]); y1[0][3]=fmaf(a0,b3,y1[0][3]);
        y1[1][0]=fmaf(a1,b0,y1[1][0]); y1[1][1]=fmaf(a1,b1,y1[1][1]);
        y1[1][2]=fmaf(a1,b2,y1[1][2]); y1[1][3]=fmaf(a1,b3,y1[1][3]);
        y1[2][0]=fmaf(a2,b0,y1[2][0]); y1[2][1]=fmaf(a2,b1,y1[2][1]);
        y1[2][2]=fmaf(a2,b2,y1[2][2]); y1[2][3]=fmaf(a2,b3,y1[2][3]);
        y1[3][0]=fmaf(a3,b0,y1[3][0]); y1[3][1]=fmaf(a3,b1,y1[3][1]);
        y1[3][2]=fmaf(a3,b2,y1[3][2]); y1[3][3]=fmaf(a3,b3,y1[3][3]);
    }
    __syncthreads();

    #pragma unroll
    for (int i = 0; i < 4; i++) {
        int n  = (tid >> 4) + i * 16;
        int c4 = (tid & 15) << 2;
        float4 hh = *(const float4*)(hp + (size_t)blk * 4096 + n*64 + c4);
        float* Hp = Buf + n*65 + c4;
        Hp[0] = hh.x; Hp[1] = hh.y; Hp[2] = hh.z; Hp[3] = hh.w;
    }
    __syncthreads();

    float y2[4][4] = {};
    #pragma unroll 8
    for (int n = 0; n < 64; n++) {
        float a0 = Csm[(ty*4+0)*65 + n];
        float a1 = Csm[(ty*4+1)*65 + n];
        float a2 = Csm[(ty*4+2)*65 + n];
        float a3 = Csm[(ty*4+3)*65 + n];
        float b0 = Buf[n*65 + tx*4 + 0];
        float b1 = Buf[n*65 + tx*4 + 1];
        float b2 = Buf[n*65 + tx*4 + 2];
        float b3 = Buf[n*65 + tx*4 + 3];
        y2[0][0]=fmaf(a0,b0,y2[0][0]); y2[0][1]=fmaf(a0,b1,y2[0][1]);
        y2[0][2]=fmaf(a0,b2,y2[0][2]); y2[0][3]=fmaf(a0,b3,y2[0][3]);
        y2[1][0]=fmaf(a1,b0,y2[1][0]); y2[1][1]=fmaf(a1,b1,y2[1][1]);
        y2[1][2]=fmaf(a1,b2,y2[1][2]); y2[1][3]=fmaf(a1,b3,y2[1][3]);
        y2[2][0]=fmaf(a2,b0,y2[2][0]); y2[2][1]=fmaf(a2,b1,y2[2][1]);
        y2[2][2]=fmaf(a2,b2,y2[2][2]); y2[2][3]=fmaf(a2,b3,y2[2][3]);
        y2[3][0]=fmaf(a3,b0,y2[3][0]); y2[3][1]=fmaf(a3,b1,y2[3][1]);
        y2[3][2]=fmaf(a3,b2,y2[3][2]); y2[3][3]=fmaf(a3,b3,y2[3][3]);
    }

    float d0 = Dv[h*64 + tx*4 + 0];
    float d1 = Dv[h*64 + tx*4 + 1];
    float d2 = Dv[h*64 + tx*4 + 2];
    float d3 = Dv[h*64 + tx*4 + 3];
    #pragma unroll
    for (int i = 0; i < 4; i++) {
        int t_ = ty*4 + i;
        int p = c * Q_ + t_;
        int l = dir ? (L_ - 1 - p) : p;
        float lam = __expf(A * csh[t_]);
        const float* row = proj + (size_t)(b * L_ + l) * PROJ_;
        float4 zz = *(const float4*)(row + h*64 + tx*4);
        float xr0 = Xsm[t_*65 + tx*4 + 0];
        float xr1 = Xsm[t_*65 + tx*4 + 1];
        float xr2 = Xsm[t_*65 + tx*4 + 2];
        float xr3 = Xsm[t_*65 + tx*4 + 3];
        float4 o;
        float yv;
        yv = y1[i][0] + lam * y2[i][0] + d0 * xr0;
        o.x = f2tff(yv * (zz.x / (1.f + __expf(-zz.x))));
        yv = y1[i][1] + lam * y2[i][1] + d1 * xr1;
        o.y = f2tff(yv * (zz.y / (1.f + __expf(-zz.y))));
        yv = y1[i][2] + lam * y2[i][2] + d2 * xr2;
        o.z = f2tff(yv * (zz.z / (1.f + __expf(-zz.z))));
        yv = y1[i][3] + lam * y2[i][3] + d3 * xr3;
        o.w = f2tff(yv * (zz.w / (1.f + __expf(-zz.w))));
        *(float4*)(gated + (size_t)(b * L_ + l) * DI2_ + dir*DI_ + h*64 + tx*4) = o;
    }
}

// ---------------- host launch ----------------
static float* sym(const void* s) {
    void* p = nullptr;
    cudaGetSymbolAddress(&p, s);
    return (float*)p;
}

extern "C" void kernel_launch(void* const* d_in, const int* in_sizes, int n_in,
                              void* d_out, int out_size) {
    const float* points = (const float*)d_in[0];
    const float* g1  = (const float*)d_in[1];
    const float* be1 = (const float*)d_in[2];
    const float* g2  = (const float*)d_in[3];
    const float* be2 = (const float*)d_in[4];
    const float* Winf  = (const float*)d_in[5];
    const float* binf  = (const float*)d_in[6];
    const float* dtbf  = (const float*)d_in[7];
    const float* Alogf = (const float*)d_in[8];
    const float* Df    = (const float*)d_in[9];
    const float* Woutf = (const float*)d_in[10];
    const float* boutf = (const float*)d_in[11];
    const float* Winb  = (const float*)d_in[12];
    const float* binb  = (const float*)d_in[13];
    const float* dtbb  = (const float*)d_in[14];
    const float* Alogb = (const float*)d_in[15];
    const float* Db    = (const float*)d_in[16];
    const float* Woutb = (const float*)d_in[17];
    const float* boutb = (const float*)d_in[18];
    const float* W1  = (const float*)d_in[19];
    const float* b1m = (const float*)d_in[20];
    const float* bng = (const float*)d_in[21];
    const float* bnb = (const float*)d_in[22];
    const float* W2  = (const float*)d_in[23];
    const float* b2m = (const float*)d_in[24];
    float* out = (float*)d_out;

    float* xln   = sym(g_xln);
    float* projf = sym(g_projf);
    float* projb = sym(g_projb);
    float* gated = sym(g_gated);
    float* x2    = sym(g_x2);
    float* h2    = sym(g_h2);
    float* hid   = sym(g_hid);
    float* wtf   = sym(g_wtf);
    float* wtb   = sym(g_wtb);
    float* wcatT = sym(g_wcatT);
    float* w1c   = sym(g_w1c);
    float* w2c   = sym(g_w2c);
    float* bcat  = sym(g_bcat);
    float* ST    = sym(g_ST);
    float* hp    = sym(g_hp);
    float* dts   = sym(g_dts);
    float* css   = sym(g_css);
    float* dtsum = sym(g_dtsum);

    int smemC = (3 * 64 * 65 + 128) * sizeof(float);
    cudaFuncSetAttribute(chunk_out_kernel, cudaFuncAttributeMaxDynamicSharedMemorySize, smemC);
    cudaFuncSetAttribute(gemm_kernel<0>, cudaFuncAttributeMaxDynamicSharedMemorySize, GSMEM_BYTES);
    cudaFuncSetAttribute(gemm_kernel<1>, cudaFuncAttributeMaxDynamicSharedMemorySize, GSMEM_BYTES);
    cudaFuncSetAttribute(gemm_kernel<2>, cudaFuncAttributeMaxDynamicSharedMemorySize, GSMEM_BYTES);

    // 1. LN1 (output tf32-rounded)
    ln_kernel<<<M_, 128>>>(points, g1, be1, xln);

    // 1b. weight prep: transpose (+round) and convert-copies
    dim3 tb(32, 8);
    transpose_w<<<dim3((PROJ_ + 31) / 32, (C_ + 31) / 32), tb>>>(Winf, wtf, C_, PROJ_, C_);
    transpose_w<<<dim3((PROJ_ + 31) / 32, (C_ + 31) / 32), tb>>>(Winb, wtb, C_, PROJ_, C_);
    transpose_w<<<dim3((C_ + 31) / 32, (DI_ + 31) / 32), tb>>>(Woutf, wcatT, DI_, C_, DI2_);
    transpose_w<<<dim3((C_ + 31) / 32, (DI_ + 31) / 32), tb>>>(Woutb, wcatT + DI_, DI_, C_, DI2_);
    cvt_copy<<<(HID_ * C_ / 4 + 255) / 256, 256>>>(W1, w1c, HID_ * C_);
    cvt_copy<<<(C_ * HID_ / 4 + 255) / 256, 256>>>(W2, w2c, C_ * HID_);
    prep_bias<<<(C_ + 255) / 256, 256>>>(boutf, boutb, bcat);

    // 2/3. input projections
    dim3 gproj((PROJ_ + 127) / 128, M_ / 128);
    gemm_kernel<0><<<gproj, 256, GSMEM_BYTES>>>(xln, wtf, binf, projf, M_, PROJ_, C_, nullptr, nullptr);
    gemm_kernel<0><<<gproj, 256, GSMEM_BYTES>>>(xln, wtb, binb, projb, M_, PROJ_, C_, nullptr, nullptr);

    // 4. chunked bidirectional scan
    chunk_state_kernel<<<NBLK_, 256>>>(projf, projb, dtbf, Alogf, dtbb, Alogb,
                                       ST, dts, css, dtsum);
    state_pass_kernel<<<2 * B_ * H_, 256>>>(ST, hp, dtsum, Alogf, Alogb);
    chunk_out_kernel<<<NBLK_, 256, smemC>>>(projf, projb, Alogf, Alogb, Df, Db,
                                            dts, css, hp, gated);

    // 5. fused output projection + residual -> x2
    dim3 gwout(C_ / 128, M_ / 128);
    gemm_kernel<2><<<gwout, 256, GSMEM_BYTES>>>(gated, wcatT, bcat, x2, M_, C_, DI2_, points, nullptr);

    // 6. LN2 (output tf32-rounded)
    ln_kernel<<<M_, 128>>>(x2, g2, be2, h2);

    // 7. MLP up
    dim3 gmlp1(HID_ / 128, M_ / 128);
    gemm_kernel<1><<<gmlp1, 256, GSMEM_BYTES>>>(h2, w1c, b1m, hid, M_, HID_, C_, bng, bnb);

    // 8. MLP down + residual -> d_out
    dim3 gmlp2(C_ / 128, M_ / 128);
    gemm_kernel<2><<<gmlp2, 256, GSMEM_BYTES>>>(hid, w2c, b2m, out, M_, C_, HID_, x2, nullptr);
}

// round 12
// speedup vs baseline: 1.8776x; 1.1075x over previous
#include <cuda_runtime.h>
#include <cuda_bf16.h>
#include <math.h>
#include <stdint.h>

// ---------------- problem constants ----------------
#define B_   4
#define L_   2048
#define C_   384
#define H_   12
#define N_   64
#define DI_  768
#define DI2_ 1536
#define HID_ 1536
#define PROJ_ 1676          // 2*DI + 2*N + H
#define M_   (B_*L_)        // 8192
#define EPS_ 1e-5f

#define Q_    64            // chunk length
#define NC_   32            // chunks per sequence (L/Q)
#define NBLK_ (2*B_*H_*NC_) // 3072

// ---------------- scratch (no allocations allowed) ----------------
__device__ float g_xln  [M_*C_];
__device__ float g_projf[M_*PROJ_];
__device__ float g_projb[M_*PROJ_];
__device__ float g_gated[M_*DI2_];     // [fwd(768) | bwd(768)] per row, tf32-rounded
__device__ float g_x2   [M_*C_];
__device__ float g_h2   [M_*C_];
__device__ float g_hid  [M_*HID_];
__device__ float g_wtf  [PROJ_*C_];    // Winf^T  (PROJ, C), tf32-rounded
__device__ float g_wtb  [PROJ_*C_];
__device__ float g_wcatT[C_*DI2_];     // [Woutf;Woutb]^T  (C, DI2), tf32-rounded
__device__ float g_w1c  [HID_*C_];     // W1 tf32-rounded
__device__ float g_w2c  [C_*HID_];     // W2 tf32-rounded
__device__ float g_bcat [C_];
__device__ float g_ST   [(size_t)NBLK_*64*64];
__device__ float g_hp   [(size_t)NBLK_*64*64];
__device__ float g_dts  [NBLK_*Q_];
__device__ float g_css  [NBLK_*Q_];
__device__ float g_dtsum[NBLK_];

// ---------------- helpers ----------------
__device__ __forceinline__ uint32_t smem_u32(const void* p) {
    uint32_t a;
    asm("{ .reg .u64 t; cvta.to.shared.u64 t, %1; cvt.u32.u64 %0, t; }" : "=r"(a) : "l"(p));
    return a;
}
__device__ __forceinline__ uint32_t f2tf(float f) {
    uint32_t u; asm("cvt.rna.tf32.f32 %0, %1;" : "=r"(u) : "f"(f)); return u;
}
__device__ __forceinline__ float f2tff(float f) {
    return __uint_as_float(f2tf(f));
}
__device__ __forceinline__ void mma_tf32(float& d0, float& d1, float& d2, float& d3,
                                         uint32_t a0, uint32_t a1, uint32_t a2, uint32_t a3,
                                         uint32_t b0, uint32_t b1) {
    asm volatile("mma.sync.aligned.m16n8k8.row.col.f32.tf32.tf32.f32 "
                 "{%0,%1,%2,%3}, {%4,%5,%6,%7}, {%8,%9}, {%0,%1,%2,%3};\n"
                 : "+f"(d0), "+f"(d1), "+f"(d2), "+f"(d3)
                 : "r"(a0), "r"(a1), "r"(a2), "r"(a3), "r"(b0), "r"(b1));
}
#define LDSM4(d0,d1,d2,d3,addr) \
    asm volatile("ldmatrix.sync.aligned.m8n8.x4.shared.b16 {%0,%1,%2,%3}, [%4];" \
        : "=r"(d0), "=r"(d1), "=r"(d2), "=r"(d3) : "r"(addr))
#define CP_ASYNC(dst, src) \
    asm volatile("cp.async.ca.shared.global [%0], [%1], 16;" :: "r"(dst), "l"(src))
#define CP_ASYNC_Z(dst, src, sz) \
    asm volatile("cp.async.ca.shared.global [%0], [%1], 16, %2;" :: "r"(dst), "l"(src), "r"(sz))
#define CP_COMMIT() asm volatile("cp.async.commit_group;" ::: "memory")
#define CP_WAIT1()  asm volatile("cp.async.wait_group 1;" ::: "memory")

// ---------------- block reduction (128 threads) ----------------
__device__ __forceinline__ float blockSum128(float v) {
    __shared__ float sh[4];
    int lane = threadIdx.x & 31, w = threadIdx.x >> 5;
    #pragma unroll
    for (int o = 16; o; o >>= 1) v += __shfl_xor_sync(0xffffffffu, v, o);
    if (lane == 0) sh[w] = v;
    __syncthreads();
    float r = sh[0] + sh[1] + sh[2] + sh[3];
    __syncthreads();
    return r;
}

// ---------------- LayerNorm (row of 384), output tf32-rounded ----------------
__global__ void ln_kernel(const float* __restrict__ x,
                          const float* __restrict__ g,
                          const float* __restrict__ be,
                          float* __restrict__ o) {
    size_t row = blockIdx.x;
    const float* xr = x + row * C_;
    int t = threadIdx.x;
    float v0 = xr[t], v1 = xr[t + 128], v2 = xr[t + 256];
    float mu = blockSum128(v0 + v1 + v2) * (1.f / C_);
    float d0 = v0 - mu, d1 = v1 - mu, d2 = v2 - mu;
    float var = blockSum128(d0*d0 + d1*d1 + d2*d2) * (1.f / C_);
    float inv = rsqrtf(var + EPS_);
    float* orow = o + row * C_;
    orow[t]       = f2tff(d0 * inv * g[t]       + be[t]);
    orow[t + 128] = f2tff(d1 * inv * g[t + 128] + be[t + 128]);
    orow[t + 256] = f2tff(d2 * inv * g[t + 256] + be[t + 256]);
}

// ---------------- tiled weight transpose (+ tf32 round) ---------------------
__global__ void transpose_w(const float* __restrict__ src, float* __restrict__ dst,
                            int K, int N, int dstride) {
    __shared__ float t[32][33];
    int bx = blockIdx.x * 32, by = blockIdx.y * 32;
    int x = threadIdx.x, y = threadIdx.y;            // (32, 8)
    #pragma unroll
    for (int j = 0; j < 32; j += 8) {
        int k = by + y + j, n = bx + x;
        t[y + j][x] = (k < K && n < N) ? src[(size_t)k * N + n] : 0.f;
    }
    __syncthreads();
    #pragma unroll
    for (int j = 0; j < 32; j += 8) {
        int n = bx + y + j, k = by + x;
        if (n < N && k < K) dst[(size_t)n * dstride + k] = f2tff(t[x][y + j]);
    }
}

__global__ void cvt_copy(const float* __restrict__ src, float* __restrict__ dst, int n) {
    int i = (blockIdx.x * 256 + threadIdx.x) * 4;
    if (i < n) {
        float4 v = *(const float4*)(src + i);
        v.x = f2tff(v.x); v.y = f2tff(v.y); v.z = f2tff(v.z); v.w = f2tff(v.w);
        *(float4*)(dst + i) = v;
    }
}

__global__ void prep_bias(const float* __restrict__ bf, const float* __restrict__ bb,
                          float* __restrict__ bcat) {
    int i = blockIdx.x * 256 + threadIdx.x;
    if (i < C_) bcat[i] = bf[i] + bb[i];
}

// ---------------- TF32 GEMM: cp.async 3-stage + ldmatrix --------------------
#define SA 20
#define AS_WORDS (128 * SA)
#define STAGE_WORDS (2 * AS_WORDS)
#define GSMEM_BYTES (3 * STAGE_WORDS * 4)   // 61440

template<int EPI>
__global__ __launch_bounds__(256, 2)
void gemm_kernel(const float* __restrict__ A, const float* __restrict__ Bt,
                 const float* __restrict__ bias, float* __restrict__ Cout,
                 int M, int N, int K,
                 const float* __restrict__ e1, const float* __restrict__ e2) {
    extern __shared__ uint32_t smg[];
    uint32_t sbase = smem_u32(smg);
    int tid = threadIdx.x;
    int gm0 = blockIdx.y << 7, gn0 = blockIdx.x << 7;
    int lane = tid & 31, wid = tid >> 5;
    int wm = (wid >> 2) << 6;
    int wn = (wid & 3) << 5;
    int g = lane >> 2, tg = lane & 3;

    int aoff = (wm + (lane & 15)) * SA + ((lane >> 4) << 2);
    int boff = (wn + (lane & 7) + ((lane >> 4) << 3)) * SA + (((lane >> 3) & 1) << 2);

    auto issue = [&](int kt, int stg) {
        int gk = kt << 4;
        uint32_t sA = sbase + stg * (STAGE_WORDS * 4);
        uint32_t sB = sA + AS_WORDS * 4;
        #pragma unroll
        for (int h = 0; h < 2; h++) {
            int seg = tid + (h << 8);
            int row = seg >> 2, k4 = (seg & 3) << 2;
            uint32_t da = sA + (row * SA + k4) * 4;
            const float* ga = A + (size_t)(gm0 + row) * K + gk + k4;
            CP_ASYNC(da, ga);
            uint32_t db = sB + (row * SA + k4) * 4;
            const float* gb = Bt + (size_t)(gn0 + row) * K + gk + k4;
            int sz = (gn0 + row < N) ? 16 : 0;
            CP_ASYNC_Z(db, gb, sz);
        }
    };

    float acc[4][4][4];
    #pragma unroll
    for (int i = 0; i < 4; i++)
        #pragma unroll
        for (int j = 0; j < 4; j++)
            #pragma unroll
            for (int r = 0; r < 4; r++) acc[i][j][r] = 0.f;

    int nkt = K >> 4;
    issue(0, 0); CP_COMMIT();
    issue(1, 1); CP_COMMIT();

    for (int kt = 0; kt < nkt; kt++) {
        CP_WAIT1();
        __syncthreads();
        int stg = kt % 3;
        if (kt + 2 < nkt) issue(kt + 2, (kt + 2) % 3);
        CP_COMMIT();

        uint32_t sA = sbase + stg * (STAGE_WORDS * 4);
        uint32_t sB = sA + AS_WORDS * 4;
        uint32_t aaddr = sA + aoff * 4;
        uint32_t baddr = sB + boff * 4;

        uint32_t rb[2][2][4];
        #pragma unroll
        for (int jj = 0; jj < 2; jj++)
            #pragma unroll
            for (int kh = 0; kh < 2; kh++)
                LDSM4(rb[jj][kh][0], rb[jj][kh][1], rb[jj][kh][2], rb[jj][kh][3],
                      baddr + ((jj * 16 * SA) + kh * 8) * 4);

        #pragma unroll
        for (int i = 0; i < 4; i++) {
            #pragma unroll
            for (int kh = 0; kh < 2; kh++) {
                uint32_t a0, a1, a2, a3;
                LDSM4(a0, a1, a2, a3, aaddr + ((i * 16 * SA) + kh * 8) * 4);
                #pragma unroll
                for (int j = 0; j < 4; j++) {
                    int jj = j >> 1, jl = j & 1;
                    mma_tf32(acc[i][j][0], acc[i][j][1], acc[i][j][2], acc[i][j][3],
                             a0, a1, a2, a3,
                             rb[jj][kh][jl * 2], rb[jj][kh][jl * 2 + 1]);
                }
            }
        }
    }

    const float bnrs = rsqrtf(1.f + EPS_);
    #pragma unroll
    for (int i = 0; i < 4; i++) {
        #pragma unroll
        for (int rh = 0; rh < 2; rh++) {
            int m = gm0 + wm + i * 16 + g + rh * 8;
            #pragma unroll
            for (int j = 0; j < 4; j++) {
                int n = gn0 + wn + j * 8 + 2 * tg;
                if (n < N) {
                    float v0 = acc[i][j][rh * 2 + 0] + bias[n];
                    float v1 = acc[i][j][rh * 2 + 1] + bias[n + 1];
                    if (EPI == 1) {
                        v0 = fmaxf(v0 * (e1[n] * bnrs) + e2[n], 0.f);
                        v1 = fmaxf(v1 * (e1[n + 1] * bnrs) + e2[n + 1], 0.f);
                        v0 = f2tff(v0); v1 = f2tff(v1);
                    } else if (EPI == 2) {
                        const float* rp = e1 + (size_t)m * N + n;
                        v0 += rp[0]; v1 += rp[1];
                    }
                    float2 o2 = {v0, v1};
                    *(float2*)(Cout + (size_t)m * N + n) = o2;
                }
            }
        }
    }
}

// ============ chunked selective scan ============
__global__ __launch_bounds__(256)
void chunk_state_kernel(const float* __restrict__ projf, const float* __restrict__ projb,
                        const float* __restrict__ dtbf, const float* __restrict__ Alogf,
                        const float* __restrict__ dtbb, const float* __restrict__ Alogb,
                        float* __restrict__ ST, float* __restrict__ dts,
                        float* __restrict__ css, float* __restrict__ dtsum) {
    int blk = blockIdx.x;
    int c   = blk & (NC_ - 1);
    int h   = (blk >> 5) % H_;
    int b   = (blk / (NC_ * H_)) & (B_ - 1);
    int dir = blk / (NC_ * H_ * B_);
    const float* proj = dir ? projb : projf;
    float A    = -expf((dir ? Alogb : Alogf)[h]);
    float dtbh = (dir ? dtbb : dtbf)[h];

    __shared__ float Bsm[Q_ * 65];
    __shared__ float Xw [Q_ * 65];
    __shared__ float dsh[Q_], csh[Q_];

    int tid = threadIdx.x;
    if (tid < Q_) {
        int p = c * Q_ + tid;
        int l = dir ? (L_ - 1 - p) : p;
        float raw = proj[(size_t)(b * L_ + l) * PROJ_ + 2*DI_ + 2*N_ + h] + dtbh;
        float dt = (raw > 20.f) ? raw : log1pf(__expf(raw));
        dsh[tid] = dt;
        csh[tid] = dt;
    }
    __syncthreads();
    for (int off = 1; off < Q_; off <<= 1) {
        float v = 0.f;
        if (tid < Q_ && tid >= off) v = csh[tid - off];
        __syncthreads();
        if (tid < Q_ && tid >= off) csh[tid] += v;
        __syncthreads();
    }
    float cend = csh[Q_ - 1];
    if (tid < Q_) {
        dts[blk * Q_ + tid] = dsh[tid];
        css[blk * Q_ + tid] = csh[tid];
    }
    if (tid == 0) dtsum[blk] = cend;

    #pragma unroll
    for (int i = 0; i < 4; i++) {
        int s  = (tid >> 4) + i * 16;
        int c4 = (tid & 15) << 2;
        int p = c * Q_ + s;
        int l = dir ? (L_ - 1 - p) : p;
        const float* row = proj + (size_t)(b * L_ + l) * PROJ_;
        float4 bb = *(const float4*)(row + 2*DI_ + c4);
        float4 xx = *(const float4*)(row + DI_ + h*64 + c4);
        float w = __expf(A * (cend - csh[s])) * dsh[s];
        float* Bp = Bsm + s * 65 + c4;
        Bp[0] = bb.x; Bp[1] = bb.y; Bp[2] = bb.z; Bp[3] = bb.w;
        float* Xp = Xw + s * 65 + c4;
        Xp[0] = w * xx.x; Xp[1] = w * xx.y; Xp[2] = w * xx.z; Xp[3] = w * xx.w;
    }
    __syncthreads();

    int ty = tid >> 4, tx = tid & 15;
    float acc[4][4] = {};
    #pragma unroll 8
    for (int s = 0; s < Q_; s++) {
        float a0 = Bsm[s*65 + ty*4 + 0];
        float a1 = Bsm[s*65 + ty*4 + 1];
        float a2 = Bsm[s*65 + ty*4 + 2];
        float a3 = Bsm[s*65 + ty*4 + 3];
        float b0 = Xw[s*65 + tx*4 + 0];
        float b1 = Xw[s*65 + tx*4 + 1];
        float b2 = Xw[s*65 + tx*4 + 2];
        float b3 = Xw[s*65 + tx*4 + 3];
        acc[0][0] = fmaf(a0,b0,acc[0][0]); acc[0][1] = fmaf(a0,b1,acc[0][1]);
        acc[0][2] = fmaf(a0,b2,acc[0][2]); acc[0][3] = fmaf(a0,b3,acc[0][3]);
        acc[1][0] = fmaf(a1,b0,acc[1][0]); acc[1][1] = fmaf(a1,b1,acc[1][1]);
        acc[1][2] = fmaf(a1,b2,acc[1][2]); acc[1][3] = fmaf(a1,b3,acc[1][3]);
        acc[2][0] = fmaf(a2,b0,acc[2][0]); acc[2][1] = fmaf(a2,b1,acc[2][1]);
        acc[2][2] = fmaf(a2,b2,acc[2][2]); acc[2][3] = fmaf(a2,b3,acc[2][3]);
        acc[3][0] = fmaf(a3,b0,acc[3][0]); acc[3][1] = fmaf(a3,b1,acc[3][1]);
        acc[3][2] = fmaf(a3,b2,acc[3][2]); acc[3][3] = fmaf(a3,b3,acc[3][3]);
    }
    #pragma unroll
    for (int i = 0; i < 4; i++) {
        float4 v = {acc[i][0], acc[i][1], acc[i][2], acc[i][3]};
        *(float4*)(ST + (size_t)blk * 4096 + (ty*4 + i) * 64 + tx*4) = v;
    }
}

// ---- state pass: 4-way split over the 4096 state elements ----
__global__ __launch_bounds__(256)
void state_pass_kernel(const float* __restrict__ ST, float* __restrict__ hp,
                       const float* __restrict__ dtsum,
                       const float* __restrict__ Alogf, const float* __restrict__ Alogb) {
    int bx = blockIdx.x;
    int g = bx >> 2, q = bx & 3;
    int dir = g / (B_ * H_);
    int h = g % H_;
    float A = -expf((dir ? Alogb : Alogf)[h]);
    int t = (q << 10) + threadIdx.x;
    float hreg[4];
    #pragma unroll
    for (int k = 0; k < 4; k++) hreg[k] = 0.f;
    size_t base = (size_t)g * NC_ * 4096;
    for (int cc = 0; cc < NC_; cc++) {
        size_t o = base + (size_t)cc * 4096 + t;
        float al = expf(A * dtsum[g * NC_ + cc]);
        float sv[4];
        #pragma unroll
        for (int k = 0; k < 4; k++) sv[k] = ST[o + k*256];
        #pragma unroll
        for (int k = 0; k < 4; k++) {
            hp[o + k*256] = hreg[k];
            hreg[k] = al * hreg[k] + sv[k];
        }
    }
}

// ---- chunk output via tensor cores ----
// Per block (dir,b,h,c): G = C·B^T (mma), mask+decay in regs, Y = Gm@X + diag(lam)·(C@H^T)
// smem layout (floats): Csm[64*68] | Bsm[64*68] | Gm[64*68] | Xt[64*68] | Ht[64*68] | dsh[64] csh[64] lam[64]
#define SW 68
#define CO_SMEM_FLOATS (5*64*SW + 192)
#define CO_SMEM_BYTES  (CO_SMEM_FLOATS*4)

__global__ __launch_bounds__(256)
void chunk_out_mma(const float* __restrict__ projf, const float* __restrict__ projb,
                   const float* __restrict__ Alogf, const float* __restrict__ Alogb,
                   const float* __restrict__ Df, const float* __restrict__ Db,
                   const float* __restrict__ dts, const float* __restrict__ css,
                   const float* __restrict__ hp, float* __restrict__ gated) {
    extern __shared__ float smo[];
    float* Csm = smo;
    float* Bsm = smo + 64*SW;
    float* Gm  = smo + 2*64*SW;
    float* Xt  = smo + 3*64*SW;
    float* Ht  = smo + 4*64*SW;
    float* dsh = smo + 5*64*SW;
    float* csh = dsh + 64;
    float* lamsh = csh + 64;

    int blk = blockIdx.x;
    int c   = blk & (NC_ - 1);
    int h   = (blk >> 5) % H_;
    int b   = (blk / (NC_ * H_)) & (B_ - 1);
    int dir = blk / (NC_ * H_ * B_);
    const float* proj = dir ? projb : projf;
    const float* Dv   = dir ? Db : Df;
    float A = -expf((dir ? Alogb : Alogf)[h]);

    int tid = threadIdx.x;
    int lane = tid & 31, wid = tid >> 5;
    int wm = (wid >> 1) << 4;   // 0,16,32,48
    int wn = (wid & 1) << 5;    // 0,32
    int g = lane >> 2, tg = lane & 3;

    if (tid < Q_) {
        dsh[tid] = dts[blk * Q_ + tid];
        float cv = css[blk * Q_ + tid];
        csh[tid] = cv;
        lamsh[tid] = __expf(A * cv);
    }

    // loads: C, B row-major; X, H transposed
    #pragma unroll
    for (int i = 0; i < 4; i++) {
        int s  = (tid >> 4) + i * 16;
        int c4 = (tid & 15) << 2;
        int p = c * Q_ + s;
        int l = dir ? (L_ - 1 - p) : p;
        const float* row = proj + (size_t)(b * L_ + l) * PROJ_;
        float4 cc4 = *(const float4*)(row + 2*DI_ + N_ + c4);
        float4 bb4 = *(const float4*)(row + 2*DI_ + c4);
        float4 xx4 = *(const float4*)(row + DI_ + h*64 + c4);
        float4 hh  = *(const float4*)(hp + (size_t)blk * 4096 + s*64 + c4);
        float* Cp = Csm + s*SW + c4;
        Cp[0] = f2tff(cc4.x); Cp[1] = f2tff(cc4.y); Cp[2] = f2tff(cc4.z); Cp[3] = f2tff(cc4.w);
        float* Bp = Bsm + s*SW + c4;
        Bp[0] = f2tff(bb4.x); Bp[1] = f2tff(bb4.y); Bp[2] = f2tff(bb4.z); Bp[3] = f2tff(bb4.w);
        // Xt[d][s] = X[s][d]
        Xt[(c4+0)*SW + s] = f2tff(xx4.x);
        Xt[(c4+1)*SW + s] = f2tff(xx4.y);
        Xt[(c4+2)*SW + s] = f2tff(xx4.z);
        Xt[(c4+3)*SW + s] = f2tff(xx4.w);
        // Ht[d][n] = hp[n][d]  (s here is the n-state row)
        Ht[(c4+0)*SW + s] = f2tff(hh.x);
        Ht[(c4+1)*SW + s] = f2tff(hh.y);
        Ht[(c4+2)*SW + s] = f2tff(hh.z);
        Ht[(c4+3)*SW + s] = f2tff(hh.w);
    }
    __syncthreads();

    uint32_t sb = smem_u32(smo);
    int arow = lane & 15, ak = (lane >> 4) << 2;
    int brow = (lane & 7) + ((lane >> 4) << 3), bk = ((lane >> 3) & 1) << 2;
    uint32_t aC = sb + ((wm + arow) * SW + ak) * 4;
    uint32_t aG = sb + ((2*64*SW) + (wm + arow) * SW + ak) * 4;
    uint32_t bB = sb + ((1*64*SW) + (wn + brow) * SW + bk) * 4;
    uint32_t bX = sb + ((3*64*SW) + (wn + brow) * SW + bk) * 4;
    uint32_t bH = sb + ((4*64*SW) + (wn + brow) * SW + bk) * 4;

    // ---- phase 1: G[t][s] = sum_n C[t][n] * B[s][n] ----
    float accG[4][4];
    #pragma unroll
    for (int j = 0; j < 4; j++)
        #pragma unroll
        for (int r = 0; r < 4; r++) accG[j][r] = 0.f;

    #pragma unroll
    for (int kt = 0; kt < 4; kt++) {
        int ko = kt * 16 * 4;
        uint32_t rb[2][2][4];
        #pragma unroll
        for (int jj = 0; jj < 2; jj++)
            #pragma unroll
            for (int kh = 0; kh < 2; kh++)
                LDSM4(rb[jj][kh][0], rb[jj][kh][1], rb[jj][kh][2], rb[jj][kh][3],
                      bB + (jj * 16 * SW + kh * 8) * 4 + ko);
        #pragma unroll
        for (int kh = 0; kh < 2; kh++) {
            uint32_t a0, a1, a2, a3;
            LDSM4(a0, a1, a2, a3, aC + (kh * 8) * 4 + ko);
            #pragma unroll
            for (int j = 0; j < 4; j++) {
                int jj = j >> 1, jl = j & 1;
                mma_tf32(accG[j][0], accG[j][1], accG[j][2], accG[j][3],
                         a0, a1, a2, a3, rb[jj][kh][jl*2], rb[jj][kh][jl*2+1]);
            }
        }
    }

    // ---- mask + decay, store Gm ----
    #pragma unroll
    for (int rh = 0; rh < 2; rh++) {
        int t_ = wm + g + rh * 8;
        float ct = csh[t_];
        #pragma unroll
        for (int j = 0; j < 4; j++) {
            int s0 = wn + j * 8 + 2 * tg;
            float m0 = (s0 <= t_) ? __expf(A * (ct - csh[s0])) * dsh[s0] : 0.f;
            float m1 = (s0 + 1 <= t_) ? __expf(A * (ct - csh[s0+1])) * dsh[s0+1] : 0.f;
            Gm[t_*SW + s0]     = f2tff(accG[j][rh*2]     * m0);
            Gm[t_*SW + s0 + 1] = f2tff(accG[j][rh*2 + 1] * m1);
        }
    }
    __syncthreads();

    // ---- phases 2+3: Y1 = Gm @ X  (B-op Xt[d][s]);  Y2 = C @ H (B-op Ht[d][n]) ----
    float y1[4][4], y2[4][4];
    #pragma unroll
    for (int j = 0; j < 4; j++)
        #pragma unroll
        for (int r = 0; r < 4; r++) { y1[j][r] = 0.f; y2[j][r] = 0.f; }

    #pragma unroll
    for (int kt = 0; kt < 4; kt++) {
        int ko = kt * 16 * 4;
        uint32_t rbx[2][2][4], rbh[2][2][4];
        #pragma unroll
        for (int jj = 0; jj < 2; jj++)
            #pragma unroll
            for (int kh = 0; kh < 2; kh++) {
                LDSM4(rbx[jj][kh][0], rbx[jj][kh][1], rbx[jj][kh][2], rbx[jj][kh][3],
                      bX + (jj * 16 * SW + kh * 8) * 4 + ko);
                LDSM4(rbh[jj][kh][0], rbh[jj][kh][1], rbh[jj][kh][2], rbh[jj][kh][3],
                      bH + (jj * 16 * SW + kh * 8) * 4 + ko);
            }
        #pragma unroll
        for (int kh = 0; kh < 2; kh++) {
            uint32_t g0, g1, g2, g3, c0, c1, c2, c3;
            LDSM4(g0, g1, g2, g3, aG + (kh * 8) * 4 + ko);
            LDSM4(c0, c1, c2, c3, aC + (kh * 8) * 4 + ko);
            #pragma unroll
            for (int j = 0; j < 4; j++) {
                int jj = j >> 1, jl = j & 1;
                mma_tf32(y1[j][0], y1[j][1], y1[j][2], y1[j][3],
                         g0, g1, g2, g3, rbx[jj][kh][jl*2], rbx[jj][kh][jl*2+1]);
                mma_tf32(y2[j][0], y2[j][1], y2[j][2], y2[j][3],
                         c0, c1, c2, c3, rbh[jj][kh][jl*2], rbh[jj][kh][jl*2+1]);
            }
        }
    }

    // ---- epilogue: y = y1 + lam[t]*y2 + D*x, silu(z) gate ----
    #pragma unroll
    for (int rh = 0; rh < 2; rh++) {
        int t_ = wm + g + rh * 8;
        int p = c * Q_ + t_;
        int l = dir ? (L_ - 1 - p) : p;
        float lamt = lamsh[t_];
        const float* zrow = proj + (size_t)(b * L_ + l) * PROJ_ + h*64;
        float* grow = gated + (size_t)(b * L_ + l) * DI2_ + dir*DI_ + h*64;
        #pragma unroll
        for (int j = 0; j < 4; j++) {
            int d0 = wn + j * 8 + 2 * tg;
            float xv0 = Xt[d0*SW + t_], xv1 = Xt[(d0+1)*SW + t_];
            float v0 = y1[j][rh*2]   + lamt * y2[j][rh*2]   + Dv[h*64 + d0]     * xv0;
            float v1 = y1[j][rh*2+1] + lamt * y2[j][rh*2+1] + Dv[h*64 + d0 + 1] * xv1;
            float2 zz = *(const float2*)(zrow + d0);
            float o0 = f2tff(v0 * (zz.x / (1.f + __expf(-zz.x))));
            float o1 = f2tff(v1 * (zz.y / (1.f + __expf(-zz.y))));
            float2 o2 = {o0, o1};
            *(float2*)(grow + d0) = o2;
        }
    }
}

// ---------------- host launch ----------------
static float* sym(const void* s) {
    void* p = nullptr;
    cudaGetSymbolAddress(&p, s);
    return (float*)p;
}

extern "C" void kernel_launch(void* const* d_in, const int* in_sizes, int n_in,
                              void* d_out, int out_size) {
    const float* points = (const float*)d_in[0];
    const float* g1  = (const float*)d_in[1];
    const float* be1 = (const float*)d_in[2];
    const float* g2  = (const float*)d_in[3];
    const float* be2 = (const float*)d_in[4];
    const float* Winf  = (const float*)d_in[5];
    const float* binf  = (const float*)d_in[6];
    const float* dtbf  = (const float*)d_in[7];
    const float* Alogf = (const float*)d_in[8];
    const float* Df    = (const float*)d_in[9];
    const float* Woutf = (const float*)d_in[10];
    const float* boutf = (const float*)d_in[11];
    const float* Winb  = (const float*)d_in[12];
    const float* binb  = (const float*)d_in[13];
    const float* dtbb  = (const float*)d_in[14];
    const float* Alogb = (const float*)d_in[15];
    const float* Db    = (const float*)d_in[16];
    const float* Woutb = (const float*)d_in[17];
    const float* boutb = (const float*)d_in[18];
    const float* W1  = (const float*)d_in[19];
    const float* b1m = (const float*)d_in[20];
    const float* bng = (const float*)d_in[21];
    const float* bnb = (const float*)d_in[22];
    const float* W2  = (const float*)d_in[23];
    const float* b2m = (const float*)d_in[24];
    float* out = (float*)d_out;

    float* xln   = sym(g_xln);
    float* projf = sym(g_projf);
    float* projb = sym(g_projb);
    float* gated = sym(g_gated);
    float* x2    = sym(g_x2);
    float* h2    = sym(g_h2);
    float* hid   = sym(g_hid);
    float* wtf   = sym(g_wtf);
    float* wtb   = sym(g_wtb);
    float* wcatT = sym(g_wcatT);
    float* w1c   = sym(g_w1c);
    float* w2c   = sym(g_w2c);
    float* bcat  = sym(g_bcat);
    float* ST    = sym(g_ST);
    float* hp    = sym(g_hp);
    float* dts   = sym(g_dts);
    float* css   = sym(g_css);
    float* dtsum = sym(g_dtsum);

    cudaFuncSetAttribute(chunk_out_mma, cudaFuncAttributeMaxDynamicSharedMemorySize, CO_SMEM_BYTES);
    cudaFuncSetAttribute(gemm_kernel<0>, cudaFuncAttributeMaxDynamicSharedMemorySize, GSMEM_BYTES);
    cudaFuncSetAttribute(gemm_kernel<1>, cudaFuncAttributeMaxDynamicSharedMemorySize, GSMEM_BYTES);
    cudaFuncSetAttribute(gemm_kernel<2>, cudaFuncAttributeMaxDynamicSharedMemorySize, GSMEM_BYTES);

    // 1. LN1 (output tf32-rounded)
    ln_kernel<<<M_, 128>>>(points, g1, be1, xln);

    // 1b. weight prep
    dim3 tb(32, 8);
    transpose_w<<<dim3((PROJ_ + 31) / 32, (C_ + 31) / 32), tb>>>(Winf, wtf, C_, PROJ_, C_);
    transpose_w<<<dim3((PROJ_ + 31) / 32, (C_ + 31) / 32), tb>>>(Winb, wtb, C_, PROJ_, C_);
    transpose_w<<<dim3((C_ + 31) / 32, (DI_ + 31) / 32), tb>>>(Woutf, wcatT, DI_, C_, DI2_);
    transpose_w<<<dim3((C_ + 31) / 32, (DI_ + 31) / 32), tb>>>(Woutb, wcatT + DI_, DI_, C_, DI2_);
    cvt_copy<<<(HID_ * C_ / 4 + 255) / 256, 256>>>(W1, w1c, HID_ * C_);
    cvt_copy<<<(C_ * HID_ / 4 + 255) / 256, 256>>>(W2, w2c, C_ * HID_);
    prep_bias<<<(C_ + 255) / 256, 256>>>(boutf, boutb, bcat);

    // 2/3. input projections
    dim3 gproj((PROJ_ + 127) / 128, M_ / 128);
    gemm_kernel<0><<<gproj, 256, GSMEM_BYTES>>>(xln, wtf, binf, projf, M_, PROJ_, C_, nullptr, nullptr);
    gemm_kernel<0><<<gproj, 256, GSMEM_BYTES>>>(xln, wtb, binb, projb, M_, PROJ_, C_, nullptr, nullptr);

    // 4. chunked bidirectional scan
    chunk_state_kernel<<<NBLK_, 256>>>(projf, projb, dtbf, Alogf, dtbb, Alogb,
                                       ST, dts, css, dtsum);
    state_pass_kernel<<<2 * B_ * H_ * 4, 256>>>(ST, hp, dtsum, Alogf, Alogb);
    chunk_out_mma<<<NBLK_, 256, CO_SMEM_BYTES>>>(projf, projb, Alogf, Alogb, Df, Db,
                                                 dts, css, hp, gated);

    // 5. fused output projection + residual -> x2
    dim3 gwout(C_ / 128, M_ / 128);
    gemm_kernel<2><<<gwout, 256, GSMEM_BYTES>>>(gated, wcatT, bcat, x2, M_, C_, DI2_, points, nullptr);

    // 6. LN2 (output tf32-rounded)
    ln_kernel<<<M_, 128>>>(x2, g2, be2, h2);

    // 7. MLP up
    dim3 gmlp1(HID_ / 128, M_ / 128);
    gemm_kernel<1><<<gmlp1, 256, GSMEM_BYTES>>>(h2, w1c, b1m, hid, M_, HID_, C_, bng, bnb);

    // 8. MLP down + residual -> d_out
    dim3 gmlp2(C_ / 128, M_ / 128);
    gemm_kernel<2><<<gmlp2, 256, GSMEM_BYTES>>>(hid, w2c, b2m, out, M_, C_, HID_, x2, nullptr);
}

// round 13
// speedup vs baseline: 1.9750x; 1.0519x over previous
#include <cuda_runtime.h>
#include <cuda_bf16.h>
#include <math.h>
#include <stdint.h>

// ---------------- problem constants ----------------
#define B_   4
#define L_   2048
#define C_   384
#define H_   12
#define N_   64
#define DI_  768
#define DI2_ 1536
#define HID_ 1536
#define PROJ_ 1676          // 2*DI + 2*N + H
#define P2_   3352          // fused fwd|bwd projection width
#define M_   (B_*L_)        // 8192
#define EPS_ 1e-5f

#define Q_    64            // chunk length
#define NC_   32            // chunks per sequence (L/Q)
#define NBLK_ (2*B_*H_*NC_) // 3072

// ---------------- scratch (no allocations allowed) ----------------
__device__ float g_xln  [M_*C_];
__device__ float g_proj2[(size_t)M_*P2_];   // [fwd proj | bwd proj] per row
__device__ float g_gated[M_*DI2_];
__device__ float g_x2   [M_*C_];
__device__ float g_h2   [M_*C_];
__device__ float g_hid  [M_*HID_];
__device__ float g_wcat2[(size_t)P2_*C_];   // [Winf^T ; Winb^T]  (3352, 384)
__device__ float g_wcatT[C_*DI2_];          // [Woutf;Woutb]^T  (C, DI2)
__device__ float g_w1c  [HID_*C_];
__device__ float g_w2c  [C_*HID_];
__device__ float g_bin2 [P2_];
__device__ float g_bcat [C_];
__device__ float g_ST   [(size_t)NBLK_*64*64];
__device__ float g_hp   [(size_t)NBLK_*64*64];
__device__ float g_dts  [NBLK_*Q_];
__device__ float g_css  [NBLK_*Q_];
__device__ float g_dtsum[NBLK_];

// ---------------- helpers ----------------
__device__ __forceinline__ uint32_t smem_u32(const void* p) {
    uint32_t a;
    asm("{ .reg .u64 t; cvta.to.shared.u64 t, %1; cvt.u32.u64 %0, t; }" : "=r"(a) : "l"(p));
    return a;
}
__device__ __forceinline__ uint32_t f2tf(float f) {
    uint32_t u; asm("cvt.rna.tf32.f32 %0, %1;" : "=r"(u) : "f"(f)); return u;
}
__device__ __forceinline__ float f2tff(float f) {
    return __uint_as_float(f2tf(f));
}
__device__ __forceinline__ void mma_tf32(float& d0, float& d1, float& d2, float& d3,
                                         uint32_t a0, uint32_t a1, uint32_t a2, uint32_t a3,
                                         uint32_t b0, uint32_t b1) {
    asm volatile("mma.sync.aligned.m16n8k8.row.col.f32.tf32.tf32.f32 "
                 "{%0,%1,%2,%3}, {%4,%5,%6,%7}, {%8,%9}, {%0,%1,%2,%3};\n"
                 : "+f"(d0), "+f"(d1), "+f"(d2), "+f"(d3)
                 : "r"(a0), "r"(a1), "r"(a2), "r"(a3), "r"(b0), "r"(b1));
}
#define LDSM4(d0,d1,d2,d3,addr) \
    asm volatile("ldmatrix.sync.aligned.m8n8.x4.shared.b16 {%0,%1,%2,%3}, [%4];" \
        : "=r"(d0), "=r"(d1), "=r"(d2), "=r"(d3) : "r"(addr))
#define CP_ASYNC(dst, src) \
    asm volatile("cp.async.ca.shared.global [%0], [%1], 16;" :: "r"(dst), "l"(src))
#define CP_ASYNC_Z(dst, src, sz) \
    asm volatile("cp.async.ca.shared.global [%0], [%1], 16, %2;" :: "r"(dst), "l"(src), "r"(sz))
#define CP_COMMIT() asm volatile("cp.async.commit_group;" ::: "memory")
#define CP_WAIT1()  asm volatile("cp.async.wait_group 1;" ::: "memory")

// ---------------- block reduction (128 threads) ----------------
__device__ __forceinline__ float blockSum128(float v) {
    __shared__ float sh[4];
    int lane = threadIdx.x & 31, w = threadIdx.x >> 5;
    #pragma unroll
    for (int o = 16; o; o >>= 1) v += __shfl_xor_sync(0xffffffffu, v, o);
    if (lane == 0) sh[w] = v;
    __syncthreads();
    float r = sh[0] + sh[1] + sh[2] + sh[3];
    __syncthreads();
    return r;
}

// ---------------- LayerNorm (row of 384), output tf32-rounded ----------------
__global__ void ln_kernel(const float* __restrict__ x,
                          const float* __restrict__ g,
                          const float* __restrict__ be,
                          float* __restrict__ o) {
    size_t row = blockIdx.x;
    const float* xr = x + row * C_;
    int t = threadIdx.x;
    float v0 = xr[t], v1 = xr[t + 128], v2 = xr[t + 256];
    float mu = blockSum128(v0 + v1 + v2) * (1.f / C_);
    float d0 = v0 - mu, d1 = v1 - mu, d2 = v2 - mu;
    float var = blockSum128(d0*d0 + d1*d1 + d2*d2) * (1.f / C_);
    float inv = rsqrtf(var + EPS_);
    float* orow = o + row * C_;
    orow[t]       = f2tff(d0 * inv * g[t]       + be[t]);
    orow[t + 128] = f2tff(d1 * inv * g[t + 128] + be[t + 128]);
    orow[t + 256] = f2tff(d2 * inv * g[t + 256] + be[t + 256]);
}

// ---------------- tiled weight transpose (+ tf32 round) ---------------------
__global__ void transpose_w(const float* __restrict__ src, float* __restrict__ dst,
                            int K, int N, int dstride) {
    __shared__ float t[32][33];
    int bx = blockIdx.x * 32, by = blockIdx.y * 32;
    int x = threadIdx.x, y = threadIdx.y;            // (32, 8)
    #pragma unroll
    for (int j = 0; j < 32; j += 8) {
        int k = by + y + j, n = bx + x;
        t[y + j][x] = (k < K && n < N) ? src[(size_t)k * N + n] : 0.f;
    }
    __syncthreads();
    #pragma unroll
    for (int j = 0; j < 32; j += 8) {
        int n = bx + y + j, k = by + x;
        if (n < N && k < K) dst[(size_t)n * dstride + k] = f2tff(t[x][y + j]);
    }
}

__global__ void cvt_copy2(const float* __restrict__ s1, float* __restrict__ d1,
                          const float* __restrict__ s2, float* __restrict__ d2, int n) {
    int i = (blockIdx.x * 256 + threadIdx.x) * 4;
    if (i < n) {
        float4 v = *(const float4*)(s1 + i);
        v.x = f2tff(v.x); v.y = f2tff(v.y); v.z = f2tff(v.z); v.w = f2tff(v.w);
        *(float4*)(d1 + i) = v;
        float4 u = *(const float4*)(s2 + i);
        u.x = f2tff(u.x); u.y = f2tff(u.y); u.z = f2tff(u.z); u.w = f2tff(u.w);
        *(float4*)(d2 + i) = u;
    }
}

__global__ void prep_bias2(const float* __restrict__ binf, const float* __restrict__ binb,
                           const float* __restrict__ bof, const float* __restrict__ bob,
                           float* __restrict__ bin2, float* __restrict__ bcat) {
    int i = blockIdx.x * 256 + threadIdx.x;
    if (i < PROJ_) { bin2[i] = binf[i]; bin2[PROJ_ + i] = binb[i]; }
    if (i < C_) bcat[i] = bof[i] + bob[i];
}

// ---------------- TF32 GEMM: cp.async 3-stage + ldmatrix --------------------
#define SA 20
#define AS_WORDS (128 * SA)
#define STAGE_WORDS (2 * AS_WORDS)
#define GSMEM_BYTES (3 * STAGE_WORDS * 4)   // 61440

template<int EPI>
__global__ __launch_bounds__(256, 2)
void gemm_kernel(const float* __restrict__ A, const float* __restrict__ Bt,
                 const float* __restrict__ bias, float* __restrict__ Cout,
                 int M, int N, int K,
                 const float* __restrict__ e1, const float* __restrict__ e2) {
    extern __shared__ uint32_t smg[];
    uint32_t sbase = smem_u32(smg);
    int tid = threadIdx.x;
    int gm0 = blockIdx.y << 7, gn0 = blockIdx.x << 7;
    int lane = tid & 31, wid = tid >> 5;
    int wm = (wid >> 2) << 6;
    int wn = (wid & 3) << 5;
    int g = lane >> 2, tg = lane & 3;

    int aoff = (wm + (lane & 15)) * SA + ((lane >> 4) << 2);
    int boff = (wn + (lane & 7) + ((lane >> 4) << 3)) * SA + (((lane >> 3) & 1) << 2);

    auto issue = [&](int kt, int stg) {
        int gk = kt << 4;
        uint32_t sA = sbase + stg * (STAGE_WORDS * 4);
        uint32_t sB = sA + AS_WORDS * 4;
        #pragma unroll
        for (int h = 0; h < 2; h++) {
            int seg = tid + (h << 8);
            int row = seg >> 2, k4 = (seg & 3) << 2;
            uint32_t da = sA + (row * SA + k4) * 4;
            const float* ga = A + (size_t)(gm0 + row) * K + gk + k4;
            CP_ASYNC(da, ga);
            uint32_t db = sB + (row * SA + k4) * 4;
            const float* gb = Bt + (size_t)(gn0 + row) * K + gk + k4;
            int sz = (gn0 + row < N) ? 16 : 0;
            CP_ASYNC_Z(db, gb, sz);
        }
    };

    float acc[4][4][4];
    #pragma unroll
    for (int i = 0; i < 4; i++)
        #pragma unroll
        for (int j = 0; j < 4; j++)
            #pragma unroll
            for (int r = 0; r < 4; r++) acc[i][j][r] = 0.f;

    int nkt = K >> 4;
    issue(0, 0); CP_COMMIT();
    issue(1, 1); CP_COMMIT();

    for (int kt = 0; kt < nkt; kt++) {
        CP_WAIT1();
        __syncthreads();
        int stg = kt % 3;
        if (kt + 2 < nkt) issue(kt + 2, (kt + 2) % 3);
        CP_COMMIT();

        uint32_t sA = sbase + stg * (STAGE_WORDS * 4);
        uint32_t sB = sA + AS_WORDS * 4;
        uint32_t aaddr = sA + aoff * 4;
        uint32_t baddr = sB + boff * 4;

        uint32_t rb[2][2][4];
        #pragma unroll
        for (int jj = 0; jj < 2; jj++)
            #pragma unroll
            for (int kh = 0; kh < 2; kh++)
                LDSM4(rb[jj][kh][0], rb[jj][kh][1], rb[jj][kh][2], rb[jj][kh][3],
                      baddr + ((jj * 16 * SA) + kh * 8) * 4);

        #pragma unroll
        for (int i = 0; i < 4; i++) {
            #pragma unroll
            for (int kh = 0; kh < 2; kh++) {
                uint32_t a0, a1, a2, a3;
                LDSM4(a0, a1, a2, a3, aaddr + ((i * 16 * SA) + kh * 8) * 4);
                #pragma unroll
                for (int j = 0; j < 4; j++) {
                    int jj = j >> 1, jl = j & 1;
                    mma_tf32(acc[i][j][0], acc[i][j][1], acc[i][j][2], acc[i][j][3],
                             a0, a1, a2, a3,
                             rb[jj][kh][jl * 2], rb[jj][kh][jl * 2 + 1]);
                }
            }
        }
    }

    const float bnrs = rsqrtf(1.f + EPS_);
    #pragma unroll
    for (int i = 0; i < 4; i++) {
        #pragma unroll
        for (int rh = 0; rh < 2; rh++) {
            int m = gm0 + wm + i * 16 + g + rh * 8;
            #pragma unroll
            for (int j = 0; j < 4; j++) {
                int n = gn0 + wn + j * 8 + 2 * tg;
                if (n < N) {
                    float v0 = acc[i][j][rh * 2 + 0] + bias[n];
                    float v1 = acc[i][j][rh * 2 + 1] + bias[n + 1];
                    if (EPI == 1) {
                        v0 = fmaxf(v0 * (e1[n] * bnrs) + e2[n], 0.f);
                        v1 = fmaxf(v1 * (e1[n + 1] * bnrs) + e2[n + 1], 0.f);
                        v0 = f2tff(v0); v1 = f2tff(v1);
                    } else if (EPI == 2) {
                        const float* rp = e1 + (size_t)m * N + n;
                        v0 += rp[0]; v1 += rp[1];
                    }
                    float2 o2 = {v0, v1};
                    *(float2*)(Cout + (size_t)m * N + n) = o2;
                }
            }
        }
    }
}

// ============ chunked selective scan ============
#define SW 68

// ---- chunk_state via tensor cores ----
// ST[n][d] = sum_s B[s][n] * (w_s * X[s][d]);  A-op Bt[n][s], B-op Xwt[d][s]
__global__ __launch_bounds__(256)
void chunk_state_kernel(const float* __restrict__ proj2,
                        const float* __restrict__ dtbf, const float* __restrict__ Alogf,
                        const float* __restrict__ dtbb, const float* __restrict__ Alogb,
                        float* __restrict__ ST, float* __restrict__ dts,
                        float* __restrict__ css, float* __restrict__ dtsum) {
    __shared__ float Btm[64*SW];
    __shared__ float Xwt[64*SW];
    __shared__ float dsh[Q_], csh[Q_];

    int blk = blockIdx.x;
    int c   = blk & (NC_ - 1);
    int h   = (blk >> 5) % H_;
    int b   = (blk / (NC_ * H_)) & (B_ - 1);
    int dir = blk / (NC_ * H_ * B_);
    int pbase = dir * PROJ_;
    float A    = -expf((dir ? Alogb : Alogf)[h]);
    float dtbh = (dir ? dtbb : dtbf)[h];

    int tid = threadIdx.x;
    if (tid < Q_) {
        int p = c * Q_ + tid;
        int l = dir ? (L_ - 1 - p) : p;
        float raw = proj2[(size_t)(b * L_ + l) * P2_ + pbase + 2*DI_ + 2*N_ + h] + dtbh;
        float dt = (raw > 20.f) ? raw : log1pf(__expf(raw));
        dsh[tid] = dt;
        csh[tid] = dt;
    }
    __syncthreads();
    for (int off = 1; off < Q_; off <<= 1) {
        float v = 0.f;
        if (tid < Q_ && tid >= off) v = csh[tid - off];
        __syncthreads();
        if (tid < Q_ && tid >= off) csh[tid] += v;
        __syncthreads();
    }
    float cend = csh[Q_ - 1];
    if (tid < Q_) {
        dts[blk * Q_ + tid] = dsh[tid];
        css[blk * Q_ + tid] = csh[tid];
    }
    if (tid == 0) dtsum[blk] = cend;

    // load + transpose-store (tf32-rounded)
    #pragma unroll
    for (int i = 0; i < 4; i++) {
        int s  = (tid >> 4) + i * 16;
        int c4 = (tid & 15) << 2;
        int p = c * Q_ + s;
        int l = dir ? (L_ - 1 - p) : p;
        const float* row = proj2 + (size_t)(b * L_ + l) * P2_ + pbase;
        float4 bb = *(const float4*)(row + 2*DI_ + c4);
        float4 xx = *(const float4*)(row + DI_ + h*64 + c4);
        float w = __expf(A * (cend - csh[s])) * dsh[s];
        Btm[(c4+0)*SW + s] = f2tff(bb.x);
        Btm[(c4+1)*SW + s] = f2tff(bb.y);
        Btm[(c4+2)*SW + s] = f2tff(bb.z);
        Btm[(c4+3)*SW + s] = f2tff(bb.w);
        Xwt[(c4+0)*SW + s] = f2tff(w * xx.x);
        Xwt[(c4+1)*SW + s] = f2tff(w * xx.y);
        Xwt[(c4+2)*SW + s] = f2tff(w * xx.z);
        Xwt[(c4+3)*SW + s] = f2tff(w * xx.w);
    }
    __syncthreads();

    int lane = tid & 31, wid = tid >> 5;
    int wm = (wid >> 1) << 4;   // n-dim: 0,16,32,48
    int wn = (wid & 1) << 5;    // d-dim: 0,32
    int g = lane >> 2, tg = lane & 3;
    uint32_t sb = smem_u32(Btm);
    int arow = lane & 15, ak = (lane >> 4) << 2;
    int brow = (lane & 7) + ((lane >> 4) << 3), bk = ((lane >> 3) & 1) << 2;
    uint32_t aB = sb + ((wm + arow) * SW + ak) * 4;
    uint32_t bX = smem_u32(Xwt) + ((wn + brow) * SW + bk) * 4;

    float accG[4][4];
    #pragma unroll
    for (int j = 0; j < 4; j++)
        #pragma unroll
        for (int r = 0; r < 4; r++) accG[j][r] = 0.f;

    #pragma unroll
    for (int kt = 0; kt < 4; kt++) {
        int ko = kt * 16 * 4;
        uint32_t rb[2][2][4];
        #pragma unroll
        for (int jj = 0; jj < 2; jj++)
            #pragma unroll
            for (int kh = 0; kh < 2; kh++)
                LDSM4(rb[jj][kh][0], rb[jj][kh][1], rb[jj][kh][2], rb[jj][kh][3],
                      bX + (jj * 16 * SW + kh * 8) * 4 + ko);
        #pragma unroll
        for (int kh = 0; kh < 2; kh++) {
            uint32_t a0, a1, a2, a3;
            LDSM4(a0, a1, a2, a3, aB + (kh * 8) * 4 + ko);
            #pragma unroll
            for (int j = 0; j < 4; j++) {
                int jj = j >> 1, jl = j & 1;
                mma_tf32(accG[j][0], accG[j][1], accG[j][2], accG[j][3],
                         a0, a1, a2, a3, rb[jj][kh][jl*2], rb[jj][kh][jl*2+1]);
            }
        }
    }

    #pragma unroll
    for (int rh = 0; rh < 2; rh++) {
        int n_ = wm + g + rh * 8;
        #pragma unroll
        for (int j = 0; j < 4; j++) {
            int d0 = wn + j * 8 + 2 * tg;
            float2 v = {accG[j][rh*2], accG[j][rh*2+1]};
            *(float2*)(ST + (size_t)blk * 4096 + n_ * 64 + d0) = v;
        }
    }
}

// ---- state pass: 4-way split over the 4096 state elements ----
__global__ __launch_bounds__(256)
void state_pass_kernel(const float* __restrict__ ST, float* __restrict__ hp,
                       const float* __restrict__ dtsum,
                       const float* __restrict__ Alogf, const float* __restrict__ Alogb) {
    int bx = blockIdx.x;
    int g = bx >> 2, q = bx & 3;
    int dir = g / (B_ * H_);
    int h = g % H_;
    float A = -expf((dir ? Alogb : Alogf)[h]);
    int t = (q << 10) + threadIdx.x;
    float hreg[4];
    #pragma unroll
    for (int k = 0; k < 4; k++) hreg[k] = 0.f;
    size_t base = (size_t)g * NC_ * 4096;
    for (int cc = 0; cc < NC_; cc++) {
        size_t o = base + (size_t)cc * 4096 + t;
        float al = expf(A * dtsum[g * NC_ + cc]);
        float sv[4];
        #pragma unroll
        for (int k = 0; k < 4; k++) sv[k] = ST[o + k*256];
        #pragma unroll
        for (int k = 0; k < 4; k++) {
            hp[o + k*256] = hreg[k];
            hreg[k] = al * hreg[k] + sv[k];
        }
    }
}

// ---- chunk output via tensor cores ----
#define CO_SMEM_FLOATS (5*64*SW + 192)
#define CO_SMEM_BYTES  (CO_SMEM_FLOATS*4)

__global__ __launch_bounds__(256)
void chunk_out_mma(const float* __restrict__ proj2,
                   const float* __restrict__ Alogf, const float* __restrict__ Alogb,
                   const float* __restrict__ Df, const float* __restrict__ Db,
                   const float* __restrict__ dts, const float* __restrict__ css,
                   const float* __restrict__ hp, float* __restrict__ gated) {
    extern __shared__ float smo[];
    float* Csm = smo;
    float* Bsm = smo + 64*SW;
    float* Gm  = smo + 2*64*SW;
    float* Xt  = smo + 3*64*SW;
    float* Ht  = smo + 4*64*SW;
    float* dsh = smo + 5*64*SW;
    float* csh = dsh + 64;
    float* lamsh = csh + 64;

    int blk = blockIdx.x;
    int c   = blk & (NC_ - 1);
    int h   = (blk >> 5) % H_;
    int b   = (blk / (NC_ * H_)) & (B_ - 1);
    int dir = blk / (NC_ * H_ * B_);
    int pbase = dir * PROJ_;
    const float* Dv   = dir ? Db : Df;
    float A = -expf((dir ? Alogb : Alogf)[h]);

    int tid = threadIdx.x;
    int lane = tid & 31, wid = tid >> 5;
    int wm = (wid >> 1) << 4;
    int wn = (wid & 1) << 5;
    int g = lane >> 2, tg = lane & 3;

    if (tid < Q_) {
        dsh[tid] = dts[blk * Q_ + tid];
        float cv = css[blk * Q_ + tid];
        csh[tid] = cv;
        lamsh[tid] = __expf(A * cv);
    }

    #pragma unroll
    for (int i = 0; i < 4; i++) {
        int s  = (tid >> 4) + i * 16;
        int c4 = (tid & 15) << 2;
        int p = c * Q_ + s;
        int l = dir ? (L_ - 1 - p) : p;
        const float* row = proj2 + (size_t)(b * L_ + l) * P2_ + pbase;
        float4 cc4 = *(const float4*)(row + 2*DI_ + N_ + c4);
        float4 bb4 = *(const float4*)(row + 2*DI_ + c4);
        float4 xx4 = *(const float4*)(row + DI_ + h*64 + c4);
        float4 hh  = *(const float4*)(hp + (size_t)blk * 4096 + s*64 + c4);
        float* Cp = Csm + s*SW + c4;
        Cp[0] = f2tff(cc4.x); Cp[1] = f2tff(cc4.y); Cp[2] = f2tff(cc4.z); Cp[3] = f2tff(cc4.w);
        float* Bp = Bsm + s*SW + c4;
        Bp[0] = f2tff(bb4.x); Bp[1] = f2tff(bb4.y); Bp[2] = f2tff(bb4.z); Bp[3] = f2tff(bb4.w);
        Xt[(c4+0)*SW + s] = f2tff(xx4.x);
        Xt[(c4+1)*SW + s] = f2tff(xx4.y);
        Xt[(c4+2)*SW + s] = f2tff(xx4.z);
        Xt[(c4+3)*SW + s] = f2tff(xx4.w);
        Ht[(c4+0)*SW + s] = f2tff(hh.x);
        Ht[(c4+1)*SW + s] = f2tff(hh.y);
        Ht[(c4+2)*SW + s] = f2tff(hh.z);
        Ht[(c4+3)*SW + s] = f2tff(hh.w);
    }
    __syncthreads();

    uint32_t sb = smem_u32(smo);
    int arow = lane & 15, ak = (lane >> 4) << 2;
    int brow = (lane & 7) + ((lane >> 4) << 3), bk = ((lane >> 3) & 1) << 2;
    uint32_t aC = sb + ((wm + arow) * SW + ak) * 4;
    uint32_t aG = sb + ((2*64*SW) + (wm + arow) * SW + ak) * 4;
    uint32_t bB = sb + ((1*64*SW) + (wn + brow) * SW + bk) * 4;
    uint32_t bX = sb + ((3*64*SW) + (wn + brow) * SW + bk) * 4;
    uint32_t bH = sb + ((4*64*SW) + (wn + brow) * SW + bk) * 4;

    float accG[4][4];
    #pragma unroll
    for (int j = 0; j < 4; j++)
        #pragma unroll
        for (int r = 0; r < 4; r++) accG[j][r] = 0.f;

    #pragma unroll
    for (int kt = 0; kt < 4; kt++) {
        int ko = kt * 16 * 4;
        uint32_t rb[2][2][4];
        #pragma unroll
        for (int jj = 0; jj < 2; jj++)
            #pragma unroll
            for (int kh = 0; kh < 2; kh++)
                LDSM4(rb[jj][kh][0], rb[jj][kh][1], rb[jj][kh][2], rb[jj][kh][3],
                      bB + (jj * 16 * SW + kh * 8) * 4 + ko);
        #pragma unroll
        for (int kh = 0; kh < 2; kh++) {
            uint32_t a0, a1, a2, a3;
            LDSM4(a0, a1, a2, a3, aC + (kh * 8) * 4 + ko);
            #pragma unroll
            for (int j = 0; j < 4; j++) {
                int jj = j >> 1, jl = j & 1;
                mma_tf32(accG[j][0], accG[j][1], accG[j][2], accG[j][3],
                         a0, a1, a2, a3, rb[jj][kh][jl*2], rb[jj][kh][jl*2+1]);
            }
        }
    }

    #pragma unroll
    for (int rh = 0; rh < 2; rh++) {
        int t_ = wm + g + rh * 8;
        float ct = csh[t_];
        #pragma unroll
        for (int j = 0; j < 4; j++) {
            int s0 = wn + j * 8 + 2 * tg;
            float m0 = (s0 <= t_) ? __expf(A * (ct - csh[s0])) * dsh[s0] : 0.f;
            float m1 = (s0 + 1 <= t_) ? __expf(A * (ct - csh[s0+1])) * dsh[s0+1] : 0.f;
            Gm[t_*SW + s0]     = f2tff(accG[j][rh*2]     * m0);
            Gm[t_*SW + s0 + 1] = f2tff(accG[j][rh*2 + 1] * m1);
        }
    }
    __syncthreads();

    float y1[4][4], y2[4][4];
    #pragma unroll
    for (int j = 0; j < 4; j++)
        #pragma unroll
        for (int r = 0; r < 4; r++) { y1[j][r] = 0.f; y2[j][r] = 0.f; }

    #pragma unroll
    for (int kt = 0; kt < 4; kt++) {
        int ko = kt * 16 * 4;
        uint32_t rbx[2][2][4], rbh[2][2][4];
        #pragma unroll
        for (int jj = 0; jj < 2; jj++)
            #pragma unroll
            for (int kh = 0; kh < 2; kh++) {
                LDSM4(rbx[jj][kh][0], rbx[jj][kh][1], rbx[jj][kh][2], rbx[jj][kh][3],
                      bX + (jj * 16 * SW + kh * 8) * 4 + ko);
                LDSM4(rbh[jj][kh][0], rbh[jj][kh][1], rbh[jj][kh][2], rbh[jj][kh][3],
                      bH + (jj * 16 * SW + kh * 8) * 4 + ko);
            }
        #pragma unroll
        for (int kh = 0; kh < 2; kh++) {
            uint32_t g0, g1, g2, g3, c0, c1, c2, c3;
            LDSM4(g0, g1, g2, g3, aG + (kh * 8) * 4 + ko);
            LDSM4(c0, c1, c2, c3, aC + (kh * 8) * 4 + ko);
            #pragma unroll
            for (int j = 0; j < 4; j++) {
                int jj = j >> 1, jl = j & 1;
                mma_tf32(y1[j][0], y1[j][1], y1[j][2], y1[j][3],
                         g0, g1, g2, g3, rbx[jj][kh][jl*2], rbx[jj][kh][jl*2+1]);
                mma_tf32(y2[j][0], y2[j][1], y2[j][2], y2[j][3],
                         c0, c1, c2, c3, rbh[jj][kh][jl*2], rbh[jj][kh][jl*2+1]);
            }
        }
    }

    #pragma unroll
    for (int rh = 0; rh < 2; rh++) {
        int t_ = wm + g + rh * 8;
        int p = c * Q_ + t_;
        int l = dir ? (L_ - 1 - p) : p;
        float lamt = lamsh[t_];
        const float* zrow = proj2 + (size_t)(b * L_ + l) * P2_ + pbase + h*64;
        float* grow = gated + (size_t)(b * L_ + l) * DI2_ + dir*DI_ + h*64;
        #pragma unroll
        for (int j = 0; j < 4; j++) {
            int d0 = wn + j * 8 + 2 * tg;
            float xv0 = Xt[d0*SW + t_], xv1 = Xt[(d0+1)*SW + t_];
            float v0 = y1[j][rh*2]   + lamt * y2[j][rh*2]   + Dv[h*64 + d0]     * xv0;
            float v1 = y1[j][rh*2+1] + lamt * y2[j][rh*2+1] + Dv[h*64 + d0 + 1] * xv1;
            float2 zz = *(const float2*)(zrow + d0);
            float o0 = f2tff(v0 * (zz.x / (1.f + __expf(-zz.x))));
            float o1 = f2tff(v1 * (zz.y / (1.f + __expf(-zz.y))));
            float2 o2 = {o0, o1};
            *(float2*)(grow + d0) = o2;
        }
    }
}

// ---------------- host launch ----------------
static float* sym(const void* s) {
    void* p = nullptr;
    cudaGetSymbolAddress(&p, s);
    return (float*)p;
}

extern "C" void kernel_launch(void* const* d_in, const int* in_sizes, int n_in,
                              void* d_out, int out_size) {
    const float* points = (const float*)d_in[0];
    const float* g1  = (const float*)d_in[1];
    const float* be1 = (const float*)d_in[2];
    const float* g2  = (const float*)d_in[3];
    const float* be2 = (const float*)d_in[4];
    const float* Winf  = (const float*)d_in[5];
    const float* binf  = (const float*)d_in[6];
    const float* dtbf  = (const float*)d_in[7];
    const float* Alogf = (const float*)d_in[8];
    const float* Df    = (const float*)d_in[9];
    const float* Woutf = (const float*)d_in[10];
    const float* boutf = (const float*)d_in[11];
    const float* Winb  = (const float*)d_in[12];
    const float* binb  = (const float*)d_in[13];
    const float* dtbb  = (const float*)d_in[14];
    const float* Alogb = (const float*)d_in[15];
    const float* Db    = (const float*)d_in[16];
    const float* Woutb = (const float*)d_in[17];
    const float* boutb = (const float*)d_in[18];
    const float* W1  = (const float*)d_in[19];
    const float* b1m = (const float*)d_in[20];
    const float* bng = (const float*)d_in[21];
    const float* bnb = (const float*)d_in[22];
    const float* W2  = (const float*)d_in[23];
    const float* b2m = (const float*)d_in[24];
    float* out = (float*)d_out;

    float* xln   = sym(g_xln);
    float* proj2 = sym(g_proj2);
    float* gated = sym(g_gated);
    float* x2    = sym(g_x2);
    float* h2    = sym(g_h2);
    float* hid   = sym(g_hid);
    float* wcat2 = sym(g_wcat2);
    float* wcatT = sym(g_wcatT);
    float* w1c   = sym(g_w1c);
    float* w2c   = sym(g_w2c);
    float* bin2  = sym(g_bin2);
    float* bcat  = sym(g_bcat);
    float* ST    = sym(g_ST);
    float* hp    = sym(g_hp);
    float* dts   = sym(g_dts);
    float* css   = sym(g_css);
    float* dtsum = sym(g_dtsum);

    cudaFuncSetAttribute(chunk_out_mma, cudaFuncAttributeMaxDynamicSharedMemorySize, CO_SMEM_BYTES);
    cudaFuncSetAttribute(gemm_kernel<0>, cudaFuncAttributeMaxDynamicSharedMemorySize, GSMEM_BYTES);
    cudaFuncSetAttribute(gemm_kernel<1>, cudaFuncAttributeMaxDynamicSharedMemorySize, GSMEM_BYTES);
    cudaFuncSetAttribute(gemm_kernel<2>, cudaFuncAttributeMaxDynamicSharedMemorySize, GSMEM_BYTES);

    // 1. LN1 (output tf32-rounded)
    ln_kernel<<<M_, 128>>>(points, g1, be1, xln);

    // 1b. weight prep: Win transposes into concatenated wcat2; Wout transposes; W1/W2 round
    dim3 tb(32, 8);
    transpose_w<<<dim3((PROJ_ + 31) / 32, (C_ + 31) / 32), tb>>>(Winf, wcat2, C_, PROJ_, C_);
    transpose_w<<<dim3((PROJ_ + 31) / 32, (C_ + 31) / 32), tb>>>(Winb, wcat2 + (size_t)PROJ_ * C_, C_, PROJ_, C_);
    transpose_w<<<dim3((C_ + 31) / 32, (DI_ + 31) / 32), tb>>>(Woutf, wcatT, DI_, C_, DI2_);
    transpose_w<<<dim3((C_ + 31) / 32, (DI_ + 31) / 32), tb>>>(Woutb, wcatT + DI_, DI_, C_, DI2_);
    cvt_copy2<<<(HID_ * C_ / 4 + 255) / 256, 256>>>(W1, w1c, W2, w2c, HID_ * C_);
    prep_bias2<<<(PROJ_ + 255) / 256, 256>>>(binf, binb, boutf, boutb, bin2, bcat);

    // 2. fused input projection: (8192 x 3352)
    dim3 gproj((P2_ + 127) / 128, M_ / 128);
    gemm_kernel<0><<<gproj, 256, GSMEM_BYTES>>>(xln, wcat2, bin2, proj2, M_, P2_, C_, nullptr, nullptr);

    // 3. chunked bidirectional scan
    chunk_state_kernel<<<NBLK_, 256>>>(proj2, dtbf, Alogf, dtbb, Alogb,
                                       ST, dts, css, dtsum);
    state_pass_kernel<<<2 * B_ * H_ * 4, 256>>>(ST, hp, dtsum, Alogf, Alogb);
    chunk_out_mma<<<NBLK_, 256, CO_SMEM_BYTES>>>(proj2, Alogf, Alogb, Df, Db,
                                                 dts, css, hp, gated);

    // 4. fused output projection + residual -> x2
    dim3 gwout(C_ / 128, M_ / 128);
    gemm_kernel<2><<<gwout, 256, GSMEM_BYTES>>>(gated, wcatT, bcat, x2, M_, C_, DI2_, points, nullptr);

    // 5. LN2 (output tf32-rounded)
    ln_kernel<<<M_, 128>>>(x2, g2, be2, h2);

    // 6. MLP up
    dim3 gmlp1(HID_ / 128, M_ / 128);
    gemm_kernel<1><<<gmlp1, 256, GSMEM_BYTES>>>(h2, w1c, b1m, hid, M_, HID_, C_, bng, bnb);

    // 7. MLP down + residual -> d_out
    dim3 gmlp2(C_ / 128, M_ / 128);
    gemm_kernel<2><<<gmlp2, 256, GSMEM_BYTES>>>(hid, w2c, b2m, out, M_, C_, HID_, x2, nullptr);
}

// round 17
// speedup vs baseline: 2.0032x; 1.0143x over previous
#include <cuda_runtime.h>
#include <cuda_bf16.h>
#include <math.h>
#include <stdint.h>

// ---------------- problem constants ----------------
#define B_   4
#define L_   2048
#define C_   384
#define H_   12
#define N_   64
#define DI_  768
#define DI2_ 1536
#define HID_ 1536
#define PROJ_ 1676          // 2*DI + 2*N + H
#define P2_   3352          // fused fwd|bwd projection width
#define M_   (B_*L_)        // 8192
#define EPS_ 1e-5f

#define Q_    64            // chunk length
#define NC_   32            // chunks per sequence (L/Q)
#define NBLK_ (2*B_*H_*NC_) // 3072

// ---------------- scratch (no allocations allowed) ----------------
__device__ float g_xln  [M_*C_];
__device__ float g_proj2[(size_t)M_*P2_];   // [fwd proj | bwd proj] per row
__device__ float g_gated[M_*DI2_];
__device__ float g_x2   [M_*C_];
__device__ float g_h2   [M_*C_];
__device__ float g_hid  [M_*HID_];
__device__ float g_wcat2[(size_t)P2_*C_];   // [Winf^T ; Winb^T]  (3352, 384)
__device__ float g_wcatT[C_*DI2_];          // [Woutf;Woutb]^T  (C, DI2)
__device__ float g_w1c  [HID_*C_];
__device__ float g_w2c  [C_*HID_];
__device__ float g_bin2 [P2_];
__device__ float g_bcat [C_];
__device__ float g_ST   [(size_t)NBLK_*64*64];
__device__ float g_hp   [(size_t)NBLK_*64*64];
__device__ float g_dts  [NBLK_*Q_];
__device__ float g_css  [NBLK_*Q_];
__device__ float g_dtsum[NBLK_];

// ---------------- helpers ----------------
__device__ __forceinline__ uint32_t smem_u32(const void* p) {
    uint32_t a;
    asm("{ .reg .u64 t; cvta.to.shared.u64 t, %1; cvt.u32.u64 %0, t; }" : "=r"(a) : "l"(p));
    return a;
}
__device__ __forceinline__ uint32_t f2tf(float f) {
    uint32_t u; asm("cvt.rna.tf32.f32 %0, %1;" : "=r"(u) : "f"(f)); return u;
}
__device__ __forceinline__ float f2tff(float f) {
    return __uint_as_float(f2tf(f));
}
__device__ __forceinline__ void mma_tf32(float& d0, float& d1, float& d2, float& d3,
                                         uint32_t a0, uint32_t a1, uint32_t a2, uint32_t a3,
                                         uint32_t b0, uint32_t b1) {
    asm volatile("mma.sync.aligned.m16n8k8.row.col.f32.tf32.tf32.f32 "
                 "{%0,%1,%2,%3}, {%4,%5,%6,%7}, {%8,%9}, {%0,%1,%2,%3};\n"
                 : "+f"(d0), "+f"(d1), "+f"(d2), "+f"(d3)
                 : "r"(a0), "r"(a1), "r"(a2), "r"(a3), "r"(b0), "r"(b1));
}
#define LDSM4(d0,d1,d2,d3,addr) \
    asm volatile("ldmatrix.sync.aligned.m8n8.x4.shared.b16 {%0,%1,%2,%3}, [%4];" \
        : "=r"(d0), "=r"(d1), "=r"(d2), "=r"(d3) : "r"(addr))
#define CP_ASYNC(dst, src) \
    asm volatile("cp.async.ca.shared.global [%0], [%1], 16;" :: "r"(dst), "l"(src))
#define CP_ASYNC_Z(dst, src, sz) \
    asm volatile("cp.async.ca.shared.global [%0], [%1], 16, %2;" :: "r"(dst), "l"(src), "r"(sz))
#define CP_COMMIT() asm volatile("cp.async.commit_group;" ::: "memory")
#define CP_WAIT1()  asm volatile("cp.async.wait_group 1;" ::: "memory")

// ---------------- LayerNorm: warp-per-row, shuffle-only ----------------------
__global__ __launch_bounds__(256)
void ln_kernel(const float* __restrict__ x,
               const float* __restrict__ g,
               const float* __restrict__ be,
               float* __restrict__ o) {
    int wid = threadIdx.x >> 5, lane = threadIdx.x & 31;
    size_t row = (size_t)blockIdx.x * 8 + wid;
    const float* xr = x + row * C_;
    int c0 = lane * 4;
    float4 v0 = *(const float4*)(xr + c0);
    float4 v1 = *(const float4*)(xr + c0 + 128);
    float4 v2 = *(const float4*)(xr + c0 + 256);
    float s = v0.x+v0.y+v0.z+v0.w + v1.x+v1.y+v1.z+v1.w + v2.x+v2.y+v2.z+v2.w;
    #pragma unroll
    for (int off = 16; off; off >>= 1) s += __shfl_xor_sync(0xffffffffu, s, off);
    float mu = s * (1.f / C_);
    float d[12] = {v0.x-mu, v0.y-mu, v0.z-mu, v0.w-mu,
                   v1.x-mu, v1.y-mu, v1.z-mu, v1.w-mu,
                   v2.x-mu, v2.y-mu, v2.z-mu, v2.w-mu};
    float q = 0.f;
    #pragma unroll
    for (int i = 0; i < 12; i++) q = fmaf(d[i], d[i], q);
    #pragma unroll
    for (int off = 16; off; off >>= 1) q += __shfl_xor_sync(0xffffffffu, q, off);
    float inv = rsqrtf(q * (1.f / C_) + EPS_);
    float* orow = o + row * C_;
    #pragma unroll
    for (int h = 0; h < 3; h++) {
        int c = c0 + h * 128;
        float4 gg = *(const float4*)(g + c);
        float4 bb = *(const float4*)(be + c);
        float4 ov;
        ov.x = f2tff(d[h*4+0] * inv * gg.x + bb.x);
        ov.y = f2tff(d[h*4+1] * inv * gg.y + bb.y);
        ov.z = f2tff(d[h*4+2] * inv * gg.z + bb.z);
        ov.w = f2tff(d[h*4+3] * inv * gg.w + bb.w);
        *(float4*)(orow + c) = ov;
    }
}

// ---------------- fused weight prep (one launch) -----------------------------
// jobs: [0,636) Winf->wcat2 | [636,1272) Winb | [1272,1560) Woutf | [1560,1848) Woutb
//       [1848,2424) cvt W1,W2 | [2424,2431) biases
#define PT1 636   // 53*12
#define PT3 288   // 12*24
#define PCV 576
#define PNB 7
#define PREP_BLOCKS (2*PT1 + 2*PT3 + PCV + PNB)   // 2431

__device__ __forceinline__ void transpose_dev(const float* __restrict__ src,
                                              float* __restrict__ dst,
                                              int K, int N, int dstride,
                                              int bxi, int byi) {
    __shared__ float t[32][33];
    int bx = bxi * 32, by = byi * 32;
    int x = threadIdx.x & 31, y = threadIdx.x >> 5;   // (32,8) flattened
    #pragma unroll
    for (int j = 0; j < 32; j += 8) {
        int k = by + y + j, n = bx + x;
        t[y + j][x] = (k < K && n < N) ? src[(size_t)k * N + n] : 0.f;
    }
    __syncthreads();
    #pragma unroll
    for (int j = 0; j < 32; j += 8) {
        int n = bx + y + j, k = by + x;
        if (n < N && k < K) dst[(size_t)n * dstride + k] = f2tff(t[x][y + j]);
    }
}

__global__ __launch_bounds__(256)
void prep_all(const float* __restrict__ Winf, const float* __restrict__ Winb,
              const float* __restrict__ Woutf, const float* __restrict__ Woutb,
              const float* __restrict__ W1, const float* __restrict__ W2,
              const float* __restrict__ binf, const float* __restrict__ binb,
              const float* __restrict__ bof, const float* __restrict__ bob,
              float* __restrict__ wcat2, float* __restrict__ wcatT,
              float* __restrict__ w1c, float* __restrict__ w2c,
              float* __restrict__ bin2, float* __restrict__ bcat) {
    int bx = blockIdx.x;
    if (bx < PT1) {
        transpose_dev(Winf, wcat2, C_, PROJ_, C_, bx % 53, bx / 53);
    } else if (bx < 2 * PT1) {
        int b2 = bx - PT1;
        transpose_dev(Winb, wcat2 + (size_t)PROJ_ * C_, C_, PROJ_, C_, b2 % 53, b2 / 53);
    } else if (bx < 2 * PT1 + PT3) {
        int b2 = bx - 2 * PT1;
        transpose_dev(Woutf, wcatT, DI_, C_, DI2_, b2 % 12, b2 / 12);
    } else if (bx < 2 * PT1 + 2 * PT3) {
        int b2 = bx - 2 * PT1 - PT3;
        transpose_dev(Woutb, wcatT + DI_, DI_, C_, DI2_, b2 % 12, b2 / 12);
    } else if (bx < 2 * PT1 + 2 * PT3 + PCV) {
        int b2 = bx - 2 * PT1 - 2 * PT3;
        int i = (b2 * 256 + threadIdx.x) * 4;
        if (i < HID_ * C_) {
            float4 v = *(const float4*)(W1 + i);
            v.x = f2tff(v.x); v.y = f2tff(v.y); v.z = f2tff(v.z); v.w = f2tff(v.w);
            *(float4*)(w1c + i) = v;
            float4 u = *(const float4*)(W2 + i);
            u.x = f2tff(u.x); u.y = f2tff(u.y); u.z = f2tff(u.z); u.w = f2tff(u.w);
            *(float4*)(w2c + i) = u;
        }
    } else {
        int b2 = bx - 2 * PT1 - 2 * PT3 - PCV;
        int i = b2 * 256 + threadIdx.x;
        if (i < PROJ_) { bin2[i] = binf[i]; bin2[PROJ_ + i] = binb[i]; }
        if (i < C_) bcat[i] = bof[i] + bob[i];
    }
}

// ---------------- TF32 GEMM: cp.async 3-stage + ldmatrix --------------------
#define SA 20
#define AS_WORDS (128 * SA)
#define STAGE_WORDS (2 * AS_WORDS)
#define GSMEM_BYTES (3 * STAGE_WORDS * 4)   // 61440

template<int EPI>
__global__ __launch_bounds__(256, 2)
void gemm_kernel(const float* __restrict__ A, const float* __restrict__ Bt,
                 const float* __restrict__ bias, float* __restrict__ Cout,
                 int M, int N, int K,
                 const float* __restrict__ e1, const float* __restrict__ e2) {
    extern __shared__ uint32_t smg[];
    uint32_t sbase = smem_u32(smg);
    int tid = threadIdx.x;
    int gm0 = blockIdx.y << 7, gn0 = blockIdx.x << 7;
    int lane = tid & 31, wid = tid >> 5;
    int wm = (wid >> 2) << 6;
    int wn = (wid & 3) << 5;
    int g = lane >> 2, tg = lane & 3;

    int aoff = (wm + (lane & 15)) * SA + ((lane >> 4) << 2);
    int boff = (wn + (lane & 7) + ((lane >> 4) << 3)) * SA + (((lane >> 3) & 1) << 2);

    auto issue = [&](int kt, int stg) {
        int gk = kt << 4;
        uint32_t sA = sbase + stg * (STAGE_WORDS * 4);
        uint32_t sB = sA + AS_WORDS * 4;
        #pragma unroll
        for (int h = 0; h < 2; h++) {
            int seg = tid + (h << 8);
            int row = seg >> 2, k4 = (seg & 3) << 2;
            uint32_t da = sA + (row * SA + k4) * 4;
            const float* ga = A + (size_t)(gm0 + row) * K + gk + k4;
            CP_ASYNC(da, ga);
            uint32_t db = sB + (row * SA + k4) * 4;
            const float* gb = Bt + (size_t)(gn0 + row) * K + gk + k4;
            int sz = (gn0 + row < N) ? 16 : 0;
            CP_ASYNC_Z(db, gb, sz);
        }
    };

    float acc[4][4][4];
    #pragma unroll
    for (int i = 0; i < 4; i++)
        #pragma unroll
        for (int j = 0; j < 4; j++)
            #pragma unroll
            for (int r = 0; r < 4; r++) acc[i][j][r] = 0.f;

    int nkt = K >> 4;
    issue(0, 0); CP_COMMIT();
    issue(1, 1); CP_COMMIT();

    for (int kt = 0; kt < nkt; kt++) {
        CP_WAIT1();
        __syncthreads();
        int stg = kt % 3;
        if (kt + 2 < nkt) issue(kt + 2, (kt + 2) % 3);
        CP_COMMIT();

        uint32_t sA = sbase + stg * (STAGE_WORDS * 4);
        uint32_t sB = sA + AS_WORDS * 4;
        uint32_t aaddr = sA + aoff * 4;
        uint32_t baddr = sB + boff * 4;

        uint32_t rb[2][2][4];
        #pragma unroll
        for (int jj = 0; jj < 2; jj++)
            #pragma unroll
            for (int kh = 0; kh < 2; kh++)
                LDSM4(rb[jj][kh][0], rb[jj][kh][1], rb[jj][kh][2], rb[jj][kh][3],
                      baddr + ((jj * 16 * SA) + kh * 8) * 4);

        #pragma unroll
        for (int i = 0; i < 4; i++) {
            #pragma unroll
            for (int kh = 0; kh < 2; kh++) {
                uint32_t a0, a1, a2, a3;
                LDSM4(a0, a1, a2, a3, aaddr + ((i * 16 * SA) + kh * 8) * 4);
                #pragma unroll
                for (int j = 0; j < 4; j++) {
                    int jj = j >> 1, jl = j & 1;
                    mma_tf32(acc[i][j][0], acc[i][j][1], acc[i][j][2], acc[i][j][3],
                             a0, a1, a2, a3,
                             rb[jj][kh][jl * 2], rb[jj][kh][jl * 2 + 1]);
                }
            }
        }
    }

    const float bnrs = rsqrtf(1.f + EPS_);
    #pragma unroll
    for (int i = 0; i < 4; i++) {
        #pragma unroll
        for (int rh = 0; rh < 2; rh++) {
            int m = gm0 + wm + i * 16 + g + rh * 8;
            #pragma unroll
            for (int j = 0; j < 4; j++) {
                int n = gn0 + wn + j * 8 + 2 * tg;
                if (n < N) {
                    float v0 = acc[i][j][rh * 2 + 0] + bias[n];
                    float v1 = acc[i][j][rh * 2 + 1] + bias[n + 1];
                    if (EPI == 1) {
                        v0 = fmaxf(v0 * (e1[n] * bnrs) + e2[n], 0.f);
                        v1 = fmaxf(v1 * (e1[n + 1] * bnrs) + e2[n + 1], 0.f);
                        v0 = f2tff(v0); v1 = f2tff(v1);
                    } else if (EPI == 2) {
                        const float* rp = e1 + (size_t)m * N + n;
                        v0 += rp[0]; v1 += rp[1];
                    }
                    float2 o2 = {v0, v1};
                    *(float2*)(Cout + (size_t)m * N + n) = o2;
                }
            }
        }
    }
}

// ============ chunked selective scan ============
#define SW 68

// ---- chunk_state via tensor cores ----
__global__ __launch_bounds__(256)
void chunk_state_kernel(const float* __restrict__ proj2,
                        const float* __restrict__ dtbf, const float* __restrict__ Alogf,
                        const float* __restrict__ dtbb, const float* __restrict__ Alogb,
                        float* __restrict__ ST, float* __restrict__ dts,
                        float* __restrict__ css, float* __restrict__ dtsum) {
    __shared__ float Btm[64*SW];
    __shared__ float Xwt[64*SW];
    __shared__ float dsh[Q_], csh[Q_];

    int blk = blockIdx.x;
    int c   = blk & (NC_ - 1);
    int h   = (blk >> 5) % H_;
    int b   = (blk / (NC_ * H_)) & (B_ - 1);
    int dir = blk / (NC_ * H_ * B_);
    int pbase = dir * PROJ_;
    float A    = -expf((dir ? Alogb : Alogf)[h]);
    float dtbh = (dir ? dtbb : dtbf)[h];

    int tid = threadIdx.x;
    if (tid < Q_) {
        int p = c * Q_ + tid;
        int l = dir ? (L_ - 1 - p) : p;
        float raw = proj2[(size_t)(b * L_ + l) * P2_ + pbase + 2*DI_ + 2*N_ + h] + dtbh;
        float dt = (raw > 20.f) ? raw : log1pf(__expf(raw));
        dsh[tid] = dt;
        csh[tid] = dt;
    }
    __syncthreads();
    for (int off = 1; off < Q_; off <<= 1) {
        float v = 0.f;
        if (tid < Q_ && tid >= off) v = csh[tid - off];
        __syncthreads();
        if (tid < Q_ && tid >= off) csh[tid] += v;
        __syncthreads();
    }
    float cend = csh[Q_ - 1];
    if (tid < Q_) {
        dts[blk * Q_ + tid] = dsh[tid];
        css[blk * Q_ + tid] = csh[tid];
    }
    if (tid == 0) dtsum[blk] = cend;

    #pragma unroll
    for (int i = 0; i < 4; i++) {
        int s  = (tid >> 4) + i * 16;
        int c4 = (tid & 15) << 2;
        int p = c * Q_ + s;
        int l = dir ? (L_ - 1 - p) : p;
        const float* row = proj2 + (size_t)(b * L_ + l) * P2_ + pbase;
        float4 bb = *(const float4*)(row + 2*DI_ + c4);
        float4 xx = *(const float4*)(row + DI_ + h*64 + c4);
        float w = __expf(A * (cend - csh[s])) * dsh[s];
        Btm[(c4+0)*SW + s] = f2tff(bb.x);
        Btm[(c4+1)*SW + s] = f2tff(bb.y);
        Btm[(c4+2)*SW + s] = f2tff(bb.z);
        Btm[(c4+3)*SW + s] = f2tff(bb.w);
        Xwt[(c4+0)*SW + s] = f2tff(w * xx.x);
        Xwt[(c4+1)*SW + s] = f2tff(w * xx.y);
        Xwt[(c4+2)*SW + s] = f2tff(w * xx.z);
        Xwt[(c4+3)*SW + s] = f2tff(w * xx.w);
    }
    __syncthreads();

    int lane = tid & 31, wid = tid >> 5;
    int wm = (wid >> 1) << 4;
    int wn = (wid & 1) << 5;
    int g = lane >> 2, tg = lane & 3;
    uint32_t sb = smem_u32(Btm);
    int arow = lane & 15, ak = (lane >> 4) << 2;
    int brow = (lane & 7) + ((lane >> 4) << 3), bk = ((lane >> 3) & 1) << 2;
    uint32_t aB = sb + ((wm + arow) * SW + ak) * 4;
    uint32_t bX = smem_u32(Xwt) + ((wn + brow) * SW + bk) * 4;

    float accG[4][4];
    #pragma unroll
    for (int j = 0; j < 4; j++)
        #pragma unroll
        for (int r = 0; r < 4; r++) accG[j][r] = 0.f;

    #pragma unroll
    for (int kt = 0; kt < 4; kt++) {
        int ko = kt * 16 * 4;
        uint32_t rb[2][2][4];
        #pragma unroll
        for (int jj = 0; jj < 2; jj++)
            #pragma unroll
            for (int kh = 0; kh < 2; kh++)
                LDSM4(rb[jj][kh][0], rb[jj][kh][1], rb[jj][kh][2], rb[jj][kh][3],
                      bX + (jj * 16 * SW + kh * 8) * 4 + ko);
        #pragma unroll
        for (int kh = 0; kh < 2; kh++) {
            uint32_t a0, a1, a2, a3;
            LDSM4(a0, a1, a2, a3, aB + (kh * 8) * 4 + ko);
            #pragma unroll
            for (int j = 0; j < 4; j++) {
                int jj = j >> 1, jl = j & 1;
                mma_tf32(accG[j][0], accG[j][1], accG[j][2], accG[j][3],
                         a0, a1, a2, a3, rb[jj][kh][jl*2], rb[jj][kh][jl*2+1]);
            }
        }
    }

    #pragma unroll
    for (int rh = 0; rh < 2; rh++) {
        int n_ = wm + g + rh * 8;
        #pragma unroll
        for (int j = 0; j < 4; j++) {
            int d0 = wn + j * 8 + 2 * tg;
            float2 v = {accG[j][rh*2], accG[j][rh*2+1]};
            *(float2*)(ST + (size_t)blk * 4096 + n_ * 64 + d0) = v;
        }
    }
}

// ---- state pass: 4-way split, software prefetch ----
__global__ __launch_bounds__(256)
void state_pass_kernel(const float* __restrict__ ST, float* __restrict__ hp,
                       const float* __restrict__ dtsum,
                       const float* __restrict__ Alogf, const float* __restrict__ Alogb) {
    int bx = blockIdx.x;
    int g = bx >> 2, q = bx & 3;
    int dir = g / (B_ * H_);
    int h = g % H_;
    float A = -expf((dir ? Alogb : Alogf)[h]);
    int t = (q << 10) + threadIdx.x;
    float hreg[4];
    #pragma unroll
    for (int k = 0; k < 4; k++) hreg[k] = 0.f;
    size_t base = (size_t)g * NC_ * 4096 + t;

    float sv[4], nx[4];
    #pragma unroll
    for (int k = 0; k < 4; k++) sv[k] = ST[base + k*256];
    float al = expf(A * dtsum[g * NC_]);
    float aln = 0.f;

    for (int cc = 0; cc < NC_; cc++) {
        size_t o = base + (size_t)cc * 4096;
        if (cc + 1 < NC_) {
            size_t on = o + 4096;
            #pragma unroll
            for (int k = 0; k < 4; k++) nx[k] = ST[on + k*256];
            aln = expf(A * dtsum[g * NC_ + cc + 1]);
        }
        #pragma unroll
        for (int k = 0; k < 4; k++) {
            hp[o + k*256] = hreg[k];
            hreg[k] = al * hreg[k] + sv[k];
        }
        #pragma unroll
        for (int k = 0; k < 4; k++) sv[k] = nx[k];
        al = aln;
    }
}

// ---- chunk output via tensor cores ----
#define CO_SMEM_FLOATS (5*64*SW + 192)
#define CO_SMEM_BYTES  (CO_SMEM_FLOATS*4)

__global__ __launch_bounds__(256)
void chunk_out_mma(const float* __restrict__ proj2,
                   const float* __restrict__ Alogf, const float* __restrict__ Alogb,
                   const float* __restrict__ Df, const float* __restrict__ Db,
                   const float* __restrict__ dts, const float* __restrict__ css,
                   const float* __restrict__ hp, float* __restrict__ gated) {
    extern __shared__ float smo[];
    float* Csm = smo;
    float* Bsm = smo + 64*SW;
    float* Gm  = smo + 2*64*SW;
    float* Xt  = smo + 3*64*SW;
    float* Ht  = smo + 4*64*SW;
    float* dsh = smo + 5*64*SW;
    float* csh = dsh + 64;
    float* lamsh = csh + 64;

    int blk = blockIdx.x;
    int c   = blk & (NC_ - 1);
    int h   = (blk >> 5) % H_;
    int b   = (blk / (NC_ * H_)) & (B_ - 1);
    int dir = blk / (NC_ * H_ * B_);
    int pbase = dir * PROJ_;
    const float* Dv   = dir ? Db : Df;
    float A = -expf((dir ? Alogb : Alogf)[h]);

    int tid = threadIdx.x;
    int lane = tid & 31, wid = tid >> 5;
    int wm = (wid >> 1) << 4;
    int wn = (wid & 1) << 5;
    int g = lane >> 2, tg = lane & 3;

    if (tid < Q_) {
        dsh[tid] = dts[blk * Q_ + tid];
        float cv = css[blk * Q_ + tid];
        csh[tid] = cv;
        lamsh[tid] = __expf(A * cv);
    }

    #pragma unroll
    for (int i = 0; i < 4; i++) {
        int s  = (tid >> 4) + i * 16;
        int c4 = (tid & 15) << 2;
        int p = c * Q_ + s;
        int l = dir ? (L_ - 1 - p) : p;
        const float* row = proj2 + (size_t)(b * L_ + l) * P2_ + pbase;
        float4 cc4 = *(const float4*)(row + 2*DI_ + N_ + c4);
        float4 bb4 = *(const float4*)(row + 2*DI_ + c4);
        float4 xx4 = *(const float4*)(row + DI_ + h*64 + c4);
        float4 hh  = *(const float4*)(hp + (size_t)blk * 4096 + s*64 + c4);
        float* Cp = Csm + s*SW + c4;
        Cp[0] = f2tff(cc4.x); Cp[1] = f2tff(cc4.y); Cp[2] = f2tff(cc4.z); Cp[3] = f2tff(cc4.w);
        float* Bp = Bsm + s*SW + c4;
        Bp[0] = f2tff(bb4.x); Bp[1] = f2tff(bb4.y); Bp[2] = f2tff(bb4.z); Bp[3] = f2tff(bb4.w);
        Xt[(c4+0)*SW + s] = f2tff(xx4.x);
        Xt[(c4+1)*SW + s] = f2tff(xx4.y);
        Xt[(c4+2)*SW + s] = f2tff(xx4.z);
        Xt[(c4+3)*SW + s] = f2tff(xx4.w);
        Ht[(c4+0)*SW + s] = f2tff(hh.x);
        Ht[(c4+1)*SW + s] = f2tff(hh.y);
        Ht[(c4+2)*SW + s] = f2tff(hh.z);
        Ht[(c4+3)*SW + s] = f2tff(hh.w);
    }
    __syncthreads();

    uint32_t sb = smem_u32(smo);
    int arow = lane & 15, ak = (lane >> 4) << 2;
    int brow = (lane & 7) + ((lane >> 4) << 3), bk = ((lane >> 3) & 1) << 2;
    uint32_t aC = sb + ((wm + arow) * SW + ak) * 4;
    uint32_t aG = sb + ((2*64*SW) + (wm + arow) * SW + ak) * 4;
    uint32_t bB = sb + ((1*64*SW) + (wn + brow) * SW + bk) * 4;
    uint32_t bX = sb + ((3*64*SW) + (wn + brow) * SW + bk) * 4;
    uint32_t bH = sb + ((4*64*SW) + (wn + brow) * SW + bk) * 4;

    float accG[4][4];
    #pragma unroll
    for (int j = 0; j < 4; j++)
        #pragma unroll
        for (int r = 0; r < 4; r++) accG[j][r] = 0.f;

    #pragma unroll
    for (int kt = 0; kt < 4; kt++) {
        int ko = kt * 16 * 4;
        uint32_t rb[2][2][4];
        #pragma unroll
        for (int jj = 0; jj < 2; jj++)
            #pragma unroll
            for (int kh = 0; kh < 2; kh++)
                LDSM4(rb[jj][kh][0], rb[jj][kh][1], rb[jj][kh][2], rb[jj][kh][3],
                      bB + (jj * 16 * SW + kh * 8) * 4 + ko);
        #pragma unroll
        for (int kh = 0; kh < 2; kh++) {
            uint32_t a0, a1, a2, a3;
            LDSM4(a0, a1, a2, a3, aC + (kh * 8) * 4 + ko);
            #pragma unroll
            for (int j = 0; j < 4; j++) {
                int jj = j >> 1, jl = j & 1;
                mma_tf32(accG[j][0], accG[j][1], accG[j][2], accG[j][3],
                         a0, a1, a2, a3, rb[jj][kh][jl*2], rb[jj][kh][jl*2+1]);
            }
        }
    }

    #pragma unroll
    for (int rh = 0; rh < 2; rh++) {
        int t_ = wm + g + rh * 8;
        float ct = csh[t_];
        #pragma unroll
        for (int j = 0; j < 4; j++) {
            int s0 = wn + j * 8 + 2 * tg;
            float m0 = (s0 <= t_) ? __expf(A * (ct - csh[s0])) * dsh[s0] : 0.f;
            float m1 = (s0 + 1 <= t_) ? __expf(A * (ct - csh[s0+1])) * dsh[s0+1] : 0.f;
            Gm[t_*SW + s0]     = f2tff(accG[j][rh*2]     * m0);
            Gm[t_*SW + s0 + 1] = f2tff(accG[j][rh*2 + 1] * m1);
        }
    }
    __syncthreads();

    float y1[4][4], y2[4][4];
    #pragma unroll
    for (int j = 0; j < 4; j++)
        #pragma unroll
        for (int r = 0; r < 4; r++) { y1[j][r] = 0.f; y2[j][r] = 0.f; }

    #pragma unroll
    for (int kt = 0; kt < 4; kt++) {
        int ko = kt * 16 * 4;
        uint32_t rbx[2][2][4], rbh[2][2][4];
        #pragma unroll
        for (int jj = 0; jj < 2; jj++)
            #pragma unroll
            for (int kh = 0; kh < 2; kh++) {
                LDSM4(rbx[jj][kh][0], rbx[jj][kh][1], rbx[jj][kh][2], rbx[jj][kh][3],
                      bX + (jj * 16 * SW + kh * 8) * 4 + ko);
                LDSM4(rbh[jj][kh][0], rbh[jj][kh][1], rbh[jj][kh][2], rbh[jj][kh][3],
                      bH + (jj * 16 * SW + kh * 8) * 4 + ko);
            }
        #pragma unroll
        for (int kh = 0; kh < 2; kh++) {
            uint32_t g0, g1, g2, g3, c0, c1, c2, c3;
            LDSM4(g0, g1, g2, g3, aG + (kh * 8) * 4 + ko);
            LDSM4(c0, c1, c2, c3, aC + (kh * 8) * 4 + ko);
            #pragma unroll
            for (int j = 0; j < 4; j++) {
                int jj = j >> 1, jl = j & 1;
                mma_tf32(y1[j][0], y1[j][1], y1[j][2], y1[j][3],
                         g0, g1, g2, g3, rbx[jj][kh][jl*2], rbx[jj][kh][jl*2+1]);
                mma_tf32(y2[j][0], y2[j][1], y2[j][2], y2[j][3],
                         c0, c1, c2, c3, rbh[jj][kh][jl*2], rbh[jj][kh][jl*2+1]);
            }
        }
    }

    #pragma unroll
    for (int rh = 0; rh < 2; rh++) {
        int t_ = wm + g + rh * 8;
        int p = c * Q_ + t_;
        int l = dir ? (L_ - 1 - p) : p;
        float lamt = lamsh[t_];
        const float* zrow = proj2 + (size_t)(b * L_ + l) * P2_ + pbase + h*64;
        float* grow = gated + (size_t)(b * L_ + l) * DI2_ + dir*DI_ + h*64;
        #pragma unroll
        for (int j = 0; j < 4; j++) {
            int d0 = wn + j * 8 + 2 * tg;
            float xv0 = Xt[d0*SW + t_], xv1 = Xt[(d0+1)*SW + t_];
            float v0 = y1[j][rh*2]   + lamt * y2[j][rh*2]   + Dv[h*64 + d0]     * xv0;
            float v1 = y1[j][rh*2+1] + lamt * y2[j][rh*2+1] + Dv[h*64 + d0 + 1] * xv1;
            float2 zz = *(const float2*)(zrow + d0);
            float o0 = f2tff(v0 * (zz.x / (1.f + __expf(-zz.x))));
            float o1 = f2tff(v1 * (zz.y / (1.f + __expf(-zz.y))));
            float2 o2 = {o0, o1};
            *(float2*)(grow + d0) = o2;
        }
    }
}

// ---------------- host launch ----------------
static float* sym(const void* s) {
    void* p = nullptr;
    cudaGetSymbolAddress(&p, s);
    return (float*)p;
}

extern "C" void kernel_launch(void* const* d_in, const int* in_sizes, int n_in,
                              void* d_out, int out_size) {
    const float* points = (const float*)d_in[0];
    const float* g1  = (const float*)d_in[1];
    const float* be1 = (const float*)d_in[2];
    const float* g2  = (const float*)d_in[3];
    const float* be2 = (const float*)d_in[4];
    const float* Winf  = (const float*)d_in[5];
    const float* binf  = (const float*)d_in[6];
    const float* dtbf  = (const float*)d_in[7];
    const float* Alogf = (const float*)d_in[8];
    const float* Df    = (const float*)d_in[9];
    const float* Woutf = (const float*)d_in[10];
    const float* boutf = (const float*)d_in[11];
    const float* Winb  = (const float*)d_in[12];
    const float* binb  = (const float*)d_in[13];
    const float* dtbb  = (const float*)d_in[14];
    const float* Alogb = (const float*)d_in[15];
    const float* Db    = (const float*)d_in[16];
    const float* Woutb = (const float*)d_in[17];
    const float* boutb = (const float*)d_in[18];
    const float* W1  = (const float*)d_in[19];
    const float* b1m = (const float*)d_in[20];
    const float* bng = (const float*)d_in[21];
    const float* bnb = (const float*)d_in[22];
    const float* W2  = (const float*)d_in[23];
    const float* b2m = (const float*)d_in[24];
    float* out = (float*)d_out;

    float* xln   = sym(g_xln);
    float* proj2 = sym(g_proj2);
    float* gated = sym(g_gated);
    float* x2    = sym(g_x2);
    float* h2    = sym(g_h2);
    float* hid   = sym(g_hid);
    float* wcat2 = sym(g_wcat2);
    float* wcatT = sym(g_wcatT);
    float* w1c   = sym(g_w1c);
    float* w2c   = sym(g_w2c);
    float* bin2  = sym(g_bin2);
    float* bcat  = sym(g_bcat);
    float* ST    = sym(g_ST);
    float* hp    = sym(g_hp);
    float* dts   = sym(g_dts);
    float* css   = sym(g_css);
    float* dtsum = sym(g_dtsum);

    cudaFuncSetAttribute(chunk_out_mma, cudaFuncAttributeMaxDynamicSharedMemorySize, CO_SMEM_BYTES);
    cudaFuncSetAttribute(gemm_kernel<0>, cudaFuncAttributeMaxDynamicSharedMemorySize, GSMEM_BYTES);
    cudaFuncSetAttribute(gemm_kernel<1>, cudaFuncAttributeMaxDynamicSharedMemorySize, GSMEM_BYTES);
    cudaFuncSetAttribute(gemm_kernel<2>, cudaFuncAttributeMaxDynamicSharedMemorySize, GSMEM_BYTES);

    // 1. LN1 + fused weight prep (prep independent of LN)
    ln_kernel<<<M_ / 8, 256>>>(points, g1, be1, xln);
    prep_all<<<PREP_BLOCKS, 256>>>(Winf, Winb, Woutf, Woutb, W1, W2,
                                   binf, binb, boutf, boutb,
                                   wcat2, wcatT, w1c, w2c, bin2, bcat);

    // 2. fused input projection: (8192 x 3352)
    dim3 gproj((P2_ + 127) / 128, M_ / 128);
    gemm_kernel<0><<<gproj, 256, GSMEM_BYTES>>>(xln, wcat2, bin2, proj2, M_, P2_, C_, nullptr, nullptr);

    // 3. chunked bidirectional scan
    chunk_state_kernel<<<NBLK_, 256>>>(proj2, dtbf, Alogf, dtbb, Alogb,
                                       ST, dts, css, dtsum);
    state_pass_kernel<<<2 * B_ * H_ * 4, 256>>>(ST, hp, dtsum, Alogf, Alogb);
    chunk_out_mma<<<NBLK_, 256, CO_SMEM_BYTES>>>(proj2, Alogf, Alogb, Df, Db,
                                                 dts, css, hp, gated);

    // 4. fused output projection + residual -> x2
    dim3 gwout(C_ / 128, M_ / 128);
    gemm_kernel<2><<<gwout, 256, GSMEM_BYTES>>>(gated, wcatT, bcat, x2, M_, C_, DI2_, points, nullptr);

    // 5. LN2
    ln_kernel<<<M_ / 8, 256>>>(x2, g2, be2, h2);

    // 6. MLP up
    dim3 gmlp1(HID_ / 128, M_ / 128);
    gemm_kernel<1><<<gmlp1, 256, GSMEM_BYTES>>>(h2, w1c, b1m, hid, M_, HID_, C_, bng, bnb);

    // 7. MLP down + residual -> d_out
    dim3 gmlp2(C_ / 128, M_ / 128);
    gemm_kernel<2><<<gmlp2, 256, GSMEM_BYTES>>>(hid, w2c, b2m, out, M_, C_, HID_, x2, nullptr);
}